// round 6
// baseline (speedup 1.0000x reference)
#include <cuda_runtime.h>
#include <cuda_bf16.h>
#include <math.h>
#include <cstdint>

// Problem constants
#define BB 2
#define SS 2048
#define DD 1024
#define HH 16
#define HDIM 64
#define DFF 4096
#define MROWS (BB * SS)   // 4096

// ---------------------------------------------------------------------------
// PTX helpers (non-arch-suffixed features only: ldmatrix, mma.sync, cp.async)
// ---------------------------------------------------------------------------
__device__ __forceinline__ uint32_t smem_to_u32(const void* smem_ptr) {
    uint32_t addr;
    asm("{ .reg .u64 tmp; cvta.to.shared.u64 tmp, %1; cvt.u32.u64 %0, tmp; }"
        : "=r"(addr) : "l"(smem_ptr));
    return addr;
}

__device__ __forceinline__ void ldmx4(uint32_t* r, uint32_t addr) {
    asm volatile("ldmatrix.sync.aligned.m8n8.x4.shared.b16 {%0,%1,%2,%3}, [%4];"
        : "=r"(r[0]), "=r"(r[1]), "=r"(r[2]), "=r"(r[3]) : "r"(addr));
}

__device__ __forceinline__ void mma16816(float* c, const uint32_t* a,
                                         uint32_t b0, uint32_t b1) {
    asm volatile(
        "mma.sync.aligned.m16n8k16.row.col.f32.bf16.bf16.f32 "
        "{%0,%1,%2,%3}, {%4,%5,%6,%7}, {%8,%9}, {%0,%1,%2,%3};"
        : "+f"(c[0]), "+f"(c[1]), "+f"(c[2]), "+f"(c[3])
        : "r"(a[0]), "r"(a[1]), "r"(a[2]), "r"(a[3]), "r"(b0), "r"(b1));
}

#define CP_ASYNC16(smem_u32, gptr) \
    asm volatile("cp.async.cg.shared.global [%0], [%1], 16;" \
        :: "r"(smem_u32), "l"(gptr))
#define CP_ASYNC_COMMIT() asm volatile("cp.async.commit_group;" ::: "memory")
#define CP_ASYNC_WAIT2()  asm volatile("cp.async.wait_group 2;" ::: "memory")

// ---------------------------------------------------------------------------
// Scratch (device globals; no allocations allowed)
// ---------------------------------------------------------------------------
__device__ float g_q  [MROWS * DD];
__device__ float g_k  [MROWS * DD];
__device__ float g_v  [MROWS * DD];
__device__ float g_x2 [MROWS * DD];
// bf16x2-split activations
__device__ __nv_bfloat16 g_hh  [MROWS * DD],  g_hl  [MROWS * DD];
__device__ __nv_bfloat16 g_ctxh[MROWS * DD],  g_ctxl[MROWS * DD];
__device__ __nv_bfloat16 g_midh[(size_t)MROWS * DFF], g_midl[(size_t)MROWS * DFF];
// Transposed + bf16x2-split weights: [N,K]
__device__ __nv_bfloat16 g_wqh[DD * DD],  g_wql[DD * DD];
__device__ __nv_bfloat16 g_wkh[DD * DD],  g_wkl[DD * DD];
__device__ __nv_bfloat16 g_wvh[DD * DD],  g_wvl[DD * DD];
__device__ __nv_bfloat16 g_woh[DD * DD],  g_wol[DD * DD];
__device__ __nv_bfloat16 g_w1h[DD * DFF], g_w1l[DD * DFF];
__device__ __nv_bfloat16 g_w2h[DFF * DD], g_w2l[DFF * DD];

// ---------------------------------------------------------------------------
// Weight transpose + bf16x2 split: W[K,N] fp32 -> Th,Tl [N,K] bf16
// ---------------------------------------------------------------------------
__global__ void wsplit_kernel(const float* __restrict__ W,
                              __nv_bfloat16* __restrict__ Th,
                              __nv_bfloat16* __restrict__ Tl,
                              int K, int N) {
    __shared__ float tile[32][33];
    int bx = blockIdx.x;  // N/32
    int by = blockIdx.y;  // K/32
    int tx = threadIdx.x; // 32
    int ty = threadIdx.y; // 8
    #pragma unroll
    for (int i = 0; i < 4; i++)
        tile[ty + 8 * i][tx] = W[(size_t)(by * 32 + ty + 8 * i) * N + bx * 32 + tx];
    __syncthreads();
    #pragma unroll
    for (int i = 0; i < 4; i++) {
        float v = tile[tx][ty + 8 * i];
        __nv_bfloat16 h = __float2bfloat16(v);
        __nv_bfloat16 l = __float2bfloat16(v - __bfloat162float(h));
        size_t o = (size_t)(bx * 32 + ty + 8 * i) * K + by * 32 + tx;
        Th[o] = h; Tl[o] = l;
    }
}

// ---------------------------------------------------------------------------
// float -> bf16 hi/lo pair helpers
// ---------------------------------------------------------------------------
__device__ __forceinline__ void split2(float a, float b, uint32_t& hw, uint32_t& lw) {
    __nv_bfloat162 h = __floats2bfloat162_rn(a, b);
    float2 f = __bfloat1622float2(h);
    __nv_bfloat162 l = __floats2bfloat162_rn(a - f.x, b - f.y);
    hw = *reinterpret_cast<const uint32_t*>(&h);
    lw = *reinterpret_cast<const uint32_t*>(&l);
}

// ---------------------------------------------------------------------------
// LayerNorm: writes bf16 hi/lo pair
// ---------------------------------------------------------------------------
__global__ void ln_kernel(const float* __restrict__ x,
                          const float* __restrict__ gamma,
                          const float* __restrict__ beta,
                          __nv_bfloat16* __restrict__ yh,
                          __nv_bfloat16* __restrict__ yl) {
    int row = blockIdx.x;
    int tid = threadIdx.x;  // 256
    const float4* xr = reinterpret_cast<const float4*>(x + (size_t)row * DD);
    float4 v = xr[tid];

    float s  = v.x + v.y + v.z + v.w;
    float sq = v.x * v.x + v.y * v.y + v.z * v.z + v.w * v.w;
    for (int o = 16; o > 0; o >>= 1) {
        s  += __shfl_down_sync(0xffffffffu, s,  o);
        sq += __shfl_down_sync(0xffffffffu, sq, o);
    }
    __shared__ float ws[8], wq[8];
    int lane = tid & 31, warp = tid >> 5;
    if (lane == 0) { ws[warp] = s; wq[warp] = sq; }
    __syncthreads();
    __shared__ float mu_s, rstd_s;
    if (tid == 0) {
        float ts = 0.f, tq = 0.f;
        #pragma unroll
        for (int i = 0; i < 8; i++) { ts += ws[i]; tq += wq[i]; }
        float mu  = ts * (1.0f / DD);
        float var = tq * (1.0f / DD) - mu * mu;
        mu_s = mu;
        rstd_s = rsqrtf(var + 1e-5f);
    }
    __syncthreads();
    float mu = mu_s, r = rstd_s;

    float4 g4 = reinterpret_cast<const float4*>(gamma)[tid];
    float4 b4 = reinterpret_cast<const float4*>(beta)[tid];
    float o0 = (v.x - mu) * r * g4.x + b4.x;
    float o1 = (v.y - mu) * r * g4.y + b4.y;
    float o2 = (v.z - mu) * r * g4.z + b4.z;
    float o3 = (v.w - mu) * r * g4.w + b4.w;
    uint2 hw, lw;
    split2(o0, o1, hw.x, lw.x);
    split2(o2, o3, hw.y, lw.y);
    *reinterpret_cast<uint2*>(yh + (size_t)row * DD + tid * 4) = hw;
    *reinterpret_cast<uint2*>(yl + (size_t)row * DD + tid * 4) = lw;
}

__device__ __forceinline__ float gelu_exact(float v) {
    return 0.5f * v * (1.0f + erff(v * 0.70710678118654752f));
}

// ---------------------------------------------------------------------------
// mma.sync bf16x2 GEMM: C = (Ah+Al)[M,K] @ (Bh+Bl)[N,K]^T (+bias)(gelu)(+res)
// CTA 128x128, BK=64, 8 warps (2M x 4N), 3-stage cp.async pipeline.
// Stage (64KB): Ah[16K] Al[16K] Bh[16K] Bl[16K], SW128 swizzle on 128B rows.
// mode: 0 = fp32 out; 1 = fp32 out + bias + res; 2 = bf16 hi/lo out + bias + gelu
// ---------------------------------------------------------------------------
#define STAGE_BYTES 65536
#define GEMM_SMEM (3 * STAGE_BYTES)

__device__ __forceinline__ uint32_t swz(uint32_t row, uint32_t colbyte) {
    return row * 128 + (colbyte ^ ((row & 7) << 4));
}

__device__ __forceinline__ void cpa_tile(uint32_t sdst, const __nv_bfloat16* __restrict__ g,
                                         int K, int r0, int k0, int tid) {
    #pragma unroll
    for (int l = 0; l < 4; l++) {
        int f = tid + 256 * l;        // 0..1023
        int row = f >> 3, c = f & 7;
        CP_ASYNC16(sdst + swz(row, c * 16), g + (size_t)(r0 + row) * K + k0 + c * 8);
    }
}

__device__ __forceinline__ void mma_gemm_body(const __nv_bfloat16* __restrict__ Ah,
                                              const __nv_bfloat16* __restrict__ Al,
                                              const __nv_bfloat16* __restrict__ Bh,
                                              const __nv_bfloat16* __restrict__ Bl,
                                              float* __restrict__ C,
                                              __nv_bfloat16* __restrict__ Ch,
                                              __nv_bfloat16* __restrict__ Cl,
                                              int N, int K,
                                              const float* __restrict__ bias,
                                              const float* __restrict__ res,
                                              int mode) {
    extern __shared__ char smem[];
    const uint32_t smem_base = smem_to_u32(smem);
    const int tid = threadIdx.x;
    const int wid = tid >> 5, lane = tid & 31;
    const int wm = wid >> 2, wn = wid & 3;   // 2 x 4 warp grid
    const int m0 = blockIdx.y * 128, n0 = blockIdx.x * 128;
    const int lr = lane & 15, lc = lane >> 4;

    float acc[4][4][4];
    #pragma unroll
    for (int i = 0; i < 4; i++)
        #pragma unroll
        for (int j = 0; j < 4; j++)
            #pragma unroll
            for (int p = 0; p < 4; p++) acc[i][j][p] = 0.f;

    const int T = K >> 6;

    auto load_tile = [&](int t, int s) {
        uint32_t sb = smem_base + s * STAGE_BYTES;
        int k0 = t * 64;
        cpa_tile(sb,         Ah, K, m0, k0, tid);
        cpa_tile(sb + 16384, Al, K, m0, k0, tid);
        cpa_tile(sb + 32768, Bh, K, n0, k0, tid);
        cpa_tile(sb + 49152, Bl, K, n0, k0, tid);
    };

    // prologue: 2 stages in flight
    load_tile(0, 0);
    CP_ASYNC_COMMIT();
    if (T > 1) load_tile(1, 1);
    CP_ASYNC_COMMIT();

    for (int t = 0; t < T; t++) {
        if (t + 2 < T) load_tile(t + 2, (t + 2) % 3);
        CP_ASYNC_COMMIT();               // empty group when no load -> keeps count uniform
        CP_ASYNC_WAIT2();                // group t complete
        __syncthreads();

        const uint32_t sb = smem_base + (t % 3) * STAGE_BYTES;
        const uint32_t sAh = sb, sAl = sb + 16384, sBh = sb + 32768, sBl = sb + 49152;
        #pragma unroll
        for (int kg = 0; kg < 4; kg++) {
            uint32_t ah[4][4], al[4][4];
            #pragma unroll
            for (int mt = 0; mt < 4; mt++) {
                uint32_t m = wm * 64 + mt * 16 + lr;
                uint32_t off = swz(m, kg * 32 + lc * 16);
                ldmx4(ah[mt], sAh + off);
                ldmx4(al[mt], sAl + off);
            }
            uint32_t bhf[2][4], blf[2][4];
            #pragma unroll
            for (int np = 0; np < 2; np++) {
                uint32_t n = wn * 32 + np * 16 + lr;
                uint32_t off = swz(n, kg * 32 + lc * 16);
                ldmx4(bhf[np], sBh + off);
                ldmx4(blf[np], sBl + off);
            }
            #pragma unroll
            for (int mt = 0; mt < 4; mt++) {
                #pragma unroll
                for (int nt = 0; nt < 4; nt++) {
                    int np = nt >> 1, u = nt & 1;
                    mma16816(acc[mt][nt], ah[mt], bhf[np][u], bhf[np][u + 2]);
                    mma16816(acc[mt][nt], ah[mt], blf[np][u], blf[np][u + 2]);
                    mma16816(acc[mt][nt], al[mt], bhf[np][u], bhf[np][u + 2]);
                }
            }
        }
        __syncthreads();
    }

    // epilogue
    #pragma unroll
    for (int mt = 0; mt < 4; mt++) {
        #pragma unroll
        for (int nt = 0; nt < 4; nt++) {
            int r0 = m0 + wm * 64 + mt * 16 + (lane >> 2);
            int c0 = n0 + wn * 32 + nt * 8 + (lane & 3) * 2;
            float bv0 = 0.f, bv1 = 0.f;
            if (mode != 0) { bv0 = bias[c0]; bv1 = bias[c0 + 1]; }
            #pragma unroll
            for (int half = 0; half < 2; half++) {
                int r = r0 + half * 8;
                float v0 = acc[mt][nt][half * 2 + 0] + bv0;
                float v1 = acc[mt][nt][half * 2 + 1] + bv1;
                if (mode == 2) {
                    v0 = gelu_exact(v0); v1 = gelu_exact(v1);
                    uint32_t hw, lw;
                    split2(v0, v1, hw, lw);
                    *reinterpret_cast<uint32_t*>(Ch + (size_t)r * N + c0) = hw;
                    *reinterpret_cast<uint32_t*>(Cl + (size_t)r * N + c0) = lw;
                } else {
                    if (mode == 1) {
                        float2 rr = *(const float2*)(res + (size_t)r * N + c0);
                        v0 += rr.x; v1 += rr.y;
                    }
                    *(float2*)(C + (size_t)r * N + c0) = make_float2(v0, v1);
                }
            }
        }
    }
}

__global__ void __launch_bounds__(256, 1)
mma_gemm(const __nv_bfloat16* __restrict__ Ah, const __nv_bfloat16* __restrict__ Al,
         const __nv_bfloat16* __restrict__ Bh, const __nv_bfloat16* __restrict__ Bl,
         float* __restrict__ C, __nv_bfloat16* __restrict__ Ch,
         __nv_bfloat16* __restrict__ Cl, int N, int K,
         const float* __restrict__ bias, const float* __restrict__ res, int mode) {
    mma_gemm_body(Ah, Al, Bh, Bl, C, Ch, Cl, N, K, bias, res, mode);
}

__global__ void __launch_bounds__(256, 1)
mma_gemm_qkv(const __nv_bfloat16* __restrict__ Ah, const __nv_bfloat16* __restrict__ Al,
             const __nv_bfloat16* __restrict__ qh, const __nv_bfloat16* __restrict__ ql,
             const __nv_bfloat16* __restrict__ kh, const __nv_bfloat16* __restrict__ kl,
             const __nv_bfloat16* __restrict__ vh, const __nv_bfloat16* __restrict__ vl,
             float* __restrict__ q, float* __restrict__ k, float* __restrict__ v) {
    const __nv_bfloat16* Bh = (blockIdx.z == 0) ? qh : (blockIdx.z == 1) ? kh : vh;
    const __nv_bfloat16* Bl = (blockIdx.z == 0) ? ql : (blockIdx.z == 1) ? kl : vl;
    float* C = (blockIdx.z == 0) ? q : (blockIdx.z == 1) ? k : v;
    mma_gemm_body(Ah, Al, Bh, Bl, C, nullptr, nullptr, DD, DD, nullptr, nullptr, 0);
}

// ---------------------------------------------------------------------------
// Flash attention (fp32 SIMT); epilogue writes ctx as bf16 hi/lo pair.
// ---------------------------------------------------------------------------
#define ATT_SMEM (64*132*4 + 64*68*4 + 64*68*4 + 64*132*4)

__global__ void __launch_bounds__(256, 2)
flash_attn_kernel(const float* __restrict__ Q, const float* __restrict__ K,
                  const float* __restrict__ V,
                  __nv_bfloat16* __restrict__ Oh, __nv_bfloat16* __restrict__ Ol) {
    extern __shared__ float sm[];
    float* Qt = sm;
    float* Kt = Qt + 64 * 132;
    float* Vs = Kt + 64 * 68;
    float* Pt = Vs + 64 * 68;

    const int tid = threadIdx.x;
    const int tx = tid & 15;
    const int ty = tid >> 4;
    const int qt = blockIdx.x;
    const int h  = blockIdx.y & 15;
    const int b  = blockIdx.y >> 4;
    const size_t base = ((size_t)b * SS) * DD + (size_t)h * HDIM;

    #pragma unroll
    for (int l = 0; l < 8; l++) {
        int f = tid + 256 * l;
        int row = f >> 4;
        int c4  = f & 15;
        float4 v = *(const float4*)(Q + base + (size_t)(qt * 128 + row) * DD + c4 * 4);
        Qt[(c4 * 4 + 0) * 132 + row] = v.x;
        Qt[(c4 * 4 + 1) * 132 + row] = v.y;
        Qt[(c4 * 4 + 2) * 132 + row] = v.z;
        Qt[(c4 * 4 + 3) * 132 + row] = v.w;
    }

    float m_i[8], l_i[8], o[8][4];
    #pragma unroll
    for (int i = 0; i < 8; i++) {
        m_i[i] = -1e30f; l_i[i] = 0.f;
        #pragma unroll
        for (int j = 0; j < 4; j++) o[i][j] = 0.f;
    }
    __syncthreads();

    const int ktmax = 2 * qt + 1;
    for (int kt = 0; kt <= ktmax; kt++) {
        #pragma unroll
        for (int l = 0; l < 4; l++) {
            int f = tid + 256 * l;
            int row = f >> 4;
            int c4  = f & 15;
            float4 kv = *(const float4*)(K + base + (size_t)(kt * 64 + row) * DD + c4 * 4);
            Kt[(c4 * 4 + 0) * 68 + row] = kv.x;
            Kt[(c4 * 4 + 1) * 68 + row] = kv.y;
            Kt[(c4 * 4 + 2) * 68 + row] = kv.z;
            Kt[(c4 * 4 + 3) * 68 + row] = kv.w;
            float4 vv = *(const float4*)(V + base + (size_t)(kt * 64 + row) * DD + c4 * 4);
            *(float4*)(&Vs[row * 68 + c4 * 4]) = vv;
        }
        __syncthreads();

        float s[8][4];
        #pragma unroll
        for (int i = 0; i < 8; i++)
            #pragma unroll
            for (int j = 0; j < 4; j++) s[i][j] = 0.f;

        #pragma unroll
        for (int d = 0; d < 64; d++) {
            float a[8];
            *(float4*)(a)     = *(const float4*)(&Qt[d * 132 + ty * 8]);
            *(float4*)(a + 4) = *(const float4*)(&Qt[d * 132 + ty * 8 + 4]);
            float4 bb = *(const float4*)(&Kt[d * 68 + tx * 4]);
            #pragma unroll
            for (int i = 0; i < 8; i++) {
                s[i][0] = fmaf(a[i], bb.x, s[i][0]);
                s[i][1] = fmaf(a[i], bb.y, s[i][1]);
                s[i][2] = fmaf(a[i], bb.z, s[i][2]);
                s[i][3] = fmaf(a[i], bb.w, s[i][3]);
            }
        }

        const bool needmask = (kt >= 2 * qt);

        #pragma unroll
        for (int i = 0; i < 8; i++) {
            int qg = qt * 128 + ty * 8 + i;
            float rmax = -1e30f;
            #pragma unroll
            for (int j = 0; j < 4; j++) {
                float sv = s[i][j] * 0.125f;
                if (needmask && (kt * 64 + tx * 4 + j > qg)) sv = -1e30f;
                s[i][j] = sv;
                rmax = fmaxf(rmax, sv);
            }
            #pragma unroll
            for (int off = 1; off < 16; off <<= 1)
                rmax = fmaxf(rmax, __shfl_xor_sync(0xffffffffu, rmax, off));
            float mnew = fmaxf(m_i[i], rmax);
            float sc = __expf(m_i[i] - mnew);
            float rsum = 0.f;
            #pragma unroll
            for (int j = 0; j < 4; j++) {
                float p = __expf(s[i][j] - mnew);
                s[i][j] = p;
                rsum += p;
            }
            #pragma unroll
            for (int off = 1; off < 16; off <<= 1)
                rsum += __shfl_xor_sync(0xffffffffu, rsum, off);
            l_i[i] = l_i[i] * sc + rsum;
            m_i[i] = mnew;
            #pragma unroll
            for (int j = 0; j < 4; j++) {
                o[i][j] *= sc;
                Pt[(tx * 4 + j) * 132 + ty * 8 + i] = s[i][j];
            }
        }
        __syncthreads();

        #pragma unroll
        for (int kk = 0; kk < 64; kk++) {
            float a[8];
            *(float4*)(a)     = *(const float4*)(&Pt[kk * 132 + ty * 8]);
            *(float4*)(a + 4) = *(const float4*)(&Pt[kk * 132 + ty * 8 + 4]);
            float4 bb = *(const float4*)(&Vs[kk * 68 + tx * 4]);
            #pragma unroll
            for (int i = 0; i < 8; i++) {
                o[i][0] = fmaf(a[i], bb.x, o[i][0]);
                o[i][1] = fmaf(a[i], bb.y, o[i][1]);
                o[i][2] = fmaf(a[i], bb.z, o[i][2]);
                o[i][3] = fmaf(a[i], bb.w, o[i][3]);
            }
        }
        __syncthreads();
    }

    #pragma unroll
    for (int i = 0; i < 8; i++) {
        float inv = 1.0f / l_i[i];
        float v0 = o[i][0] * inv, v1 = o[i][1] * inv;
        float v2 = o[i][2] * inv, v3 = o[i][3] * inv;
        uint2 hw, lw;
        split2(v0, v1, hw.x, lw.x);
        split2(v2, v3, hw.y, lw.y);
        size_t off = base + (size_t)(qt * 128 + ty * 8 + i) * DD + tx * 4;
        *reinterpret_cast<uint2*>(Oh + off) = hw;
        *reinterpret_cast<uint2*>(Ol + off) = lw;
    }
}

// ---------------------------------------------------------------------------
// Launch
// ---------------------------------------------------------------------------
extern "C" void kernel_launch(void* const* d_in, const int* in_sizes, int n_in,
                              void* d_out, int out_size) {
    const float* x     = (const float*)d_in[0];
    const float* ln1_g = (const float*)d_in[1];
    const float* ln1_b = (const float*)d_in[2];
    const float* Wq    = (const float*)d_in[3];
    const float* Wk    = (const float*)d_in[4];
    const float* Wv    = (const float*)d_in[5];
    const float* Wo    = (const float*)d_in[6];
    const float* bo    = (const float*)d_in[7];
    const float* ln2_g = (const float*)d_in[8];
    const float* ln2_b = (const float*)d_in[9];
    const float* W1    = (const float*)d_in[10];
    const float* b1    = (const float*)d_in[11];
    const float* W2    = (const float*)d_in[12];
    const float* b2    = (const float*)d_in[13];
    float* out = (float*)d_out;

    float *q, *k, *v, *x2;
    cudaGetSymbolAddress((void**)&q,   g_q);
    cudaGetSymbolAddress((void**)&k,   g_k);
    cudaGetSymbolAddress((void**)&v,   g_v);
    cudaGetSymbolAddress((void**)&x2,  g_x2);
    __nv_bfloat16 *hh, *hl, *ctxh, *ctxl, *midh, *midl;
    cudaGetSymbolAddress((void**)&hh,   g_hh);   cudaGetSymbolAddress((void**)&hl,   g_hl);
    cudaGetSymbolAddress((void**)&ctxh, g_ctxh); cudaGetSymbolAddress((void**)&ctxl, g_ctxl);
    cudaGetSymbolAddress((void**)&midh, g_midh); cudaGetSymbolAddress((void**)&midl, g_midl);

    __nv_bfloat16 *wqh, *wql, *wkh, *wkl, *wvh, *wvl, *woh, *wol, *w1h, *w1l, *w2h, *w2l;
    cudaGetSymbolAddress((void**)&wqh, g_wqh); cudaGetSymbolAddress((void**)&wql, g_wql);
    cudaGetSymbolAddress((void**)&wkh, g_wkh); cudaGetSymbolAddress((void**)&wkl, g_wkl);
    cudaGetSymbolAddress((void**)&wvh, g_wvh); cudaGetSymbolAddress((void**)&wvl, g_wvl);
    cudaGetSymbolAddress((void**)&woh, g_woh); cudaGetSymbolAddress((void**)&wol, g_wol);
    cudaGetSymbolAddress((void**)&w1h, g_w1h); cudaGetSymbolAddress((void**)&w1l, g_w1l);
    cudaGetSymbolAddress((void**)&w2h, g_w2h); cudaGetSymbolAddress((void**)&w2l, g_w2l);

    static int attr_set = 0;
    if (!attr_set) {
        cudaFuncSetAttribute(flash_attn_kernel,
                             cudaFuncAttributeMaxDynamicSharedMemorySize, ATT_SMEM);
        cudaFuncSetAttribute(mma_gemm,
                             cudaFuncAttributeMaxDynamicSharedMemorySize, GEMM_SMEM);
        cudaFuncSetAttribute(mma_gemm_qkv,
                             cudaFuncAttributeMaxDynamicSharedMemorySize, GEMM_SMEM);
        attr_set = 1;
    }

    const int M = MROWS;
    dim3 tb(32, 8);

    // 0. weight transpose + bf16x2 split
    wsplit_kernel<<<dim3(DD / 32, DD / 32), tb>>>(Wq, wqh, wql, DD, DD);
    wsplit_kernel<<<dim3(DD / 32, DD / 32), tb>>>(Wk, wkh, wkl, DD, DD);
    wsplit_kernel<<<dim3(DD / 32, DD / 32), tb>>>(Wv, wvh, wvl, DD, DD);
    wsplit_kernel<<<dim3(DD / 32, DD / 32), tb>>>(Wo, woh, wol, DD, DD);
    wsplit_kernel<<<dim3(DFF / 32, DD / 32), tb>>>(W1, w1h, w1l, DD, DFF);
    wsplit_kernel<<<dim3(DD / 32, DFF / 32), tb>>>(W2, w2h, w2l, DFF, DD);

    // 1. LN1 -> (hh, hl)
    ln_kernel<<<M, 256>>>(x, ln1_g, ln1_b, hh, hl);

    // 2. QKV projections
    dim3 gQKV(DD / 128, M / 128, 3);
    mma_gemm_qkv<<<gQKV, 256, GEMM_SMEM>>>(hh, hl, wqh, wql, wkh, wkl, wvh, wvl, q, k, v);

    // 3. causal flash attention -> (ctxh, ctxl)
    dim3 gA(SS / 128, BB * HH);
    flash_attn_kernel<<<gA, 256, ATT_SMEM>>>(q, k, v, ctxh, ctxl);

    // 4. output projection + bias + residual(x) -> x2
    dim3 gDD(DD / 128, M / 128);
    mma_gemm<<<gDD, 256, GEMM_SMEM>>>(ctxh, ctxl, woh, wol, x2, nullptr, nullptr,
                                      DD, DD, bo, x, 1);

    // 5. LN2 -> (hh, hl)
    ln_kernel<<<M, 256>>>(x2, ln2_g, ln2_b, hh, hl);

    // 6. W1 + b1 + GELU -> (midh, midl)
    dim3 gFF(DFF / 128, M / 128);
    mma_gemm<<<gFF, 256, GEMM_SMEM>>>(hh, hl, w1h, w1l, nullptr, midh, midl,
                                      DFF, DD, b1, nullptr, 2);

    // 7. W2 + b2 + residual(x2) -> out
    mma_gemm<<<gDD, 256, GEMM_SMEM>>>(midh, midl, w2h, w2l, out, nullptr, nullptr,
                                      DD, DFF, b2, x2, 1);
}

// round 7
// speedup vs baseline: 1.0505x; 1.0505x over previous
#include <cuda_runtime.h>
#include <cuda_bf16.h>
#include <cuda_fp16.h>
#include <math.h>
#include <cstdint>

#define BB 2
#define SS 2048
#define DD 1024
#define HH 16
#define HDIM 64
#define DFF 4096
#define MROWS (BB * SS)

// ---------------- PTX helpers ----------------
__device__ __forceinline__ uint32_t smem_to_u32(const void* p) {
    uint32_t a;
    asm("{ .reg .u64 t; cvta.to.shared.u64 t, %1; cvt.u32.u64 %0, t; }" : "=r"(a) : "l"(p));
    return a;
}
__device__ __forceinline__ void ldmx4(uint32_t* r, uint32_t a) {
    asm volatile("ldmatrix.sync.aligned.m8n8.x4.shared.b16 {%0,%1,%2,%3}, [%4];"
        : "=r"(r[0]), "=r"(r[1]), "=r"(r[2]), "=r"(r[3]) : "r"(a));
}
__device__ __forceinline__ void ldmx4t(uint32_t* r, uint32_t a) {
    asm volatile("ldmatrix.sync.aligned.m8n8.x4.trans.shared.b16 {%0,%1,%2,%3}, [%4];"
        : "=r"(r[0]), "=r"(r[1]), "=r"(r[2]), "=r"(r[3]) : "r"(a));
}
__device__ __forceinline__ void mma_bf16(float* c, const uint32_t* a, uint32_t b0, uint32_t b1) {
    asm volatile("mma.sync.aligned.m16n8k16.row.col.f32.bf16.bf16.f32 "
        "{%0,%1,%2,%3}, {%4,%5,%6,%7}, {%8,%9}, {%0,%1,%2,%3};"
        : "+f"(c[0]), "+f"(c[1]), "+f"(c[2]), "+f"(c[3])
        : "r"(a[0]), "r"(a[1]), "r"(a[2]), "r"(a[3]), "r"(b0), "r"(b1));
}
__device__ __forceinline__ void mma_f16(float* c, const uint32_t* a, uint32_t b0, uint32_t b1) {
    asm volatile("mma.sync.aligned.m16n8k16.row.col.f32.f16.f16.f32 "
        "{%0,%1,%2,%3}, {%4,%5,%6,%7}, {%8,%9}, {%0,%1,%2,%3};"
        : "+f"(c[0]), "+f"(c[1]), "+f"(c[2]), "+f"(c[3])
        : "r"(a[0]), "r"(a[1]), "r"(a[2]), "r"(a[3]), "r"(b0), "r"(b1));
}
#define CP_ASYNC16(s, g) asm volatile("cp.async.cg.shared.global [%0], [%1], 16;" :: "r"(s), "l"(g))
#define CP_ASYNC_COMMIT() asm volatile("cp.async.commit_group;" ::: "memory")
#define CP_ASYNC_WAIT2()  asm volatile("cp.async.wait_group 2;" ::: "memory")
#define CP_ASYNC_WAIT1()  asm volatile("cp.async.wait_group 1;" ::: "memory")

__device__ __forceinline__ uint32_t swz(uint32_t row, uint32_t colbyte) {
    return row * 128 + (colbyte ^ ((row & 7) << 4));
}
__device__ __forceinline__ void split2(float a, float b, uint32_t& hw, uint32_t& lw) {
    __nv_bfloat162 h = __floats2bfloat162_rn(a, b);
    float2 f = __bfloat1622float2(h);
    __nv_bfloat162 l = __floats2bfloat162_rn(a - f.x, b - f.y);
    hw = *reinterpret_cast<const uint32_t*>(&h);
    lw = *reinterpret_cast<const uint32_t*>(&l);
}
__device__ __forceinline__ float gelu_exact(float v) {
    return 0.5f * v * (1.0f + erff(v * 0.70710678118654752f));
}

// ---------------- scratch ----------------
__device__ float g_x2[MROWS * DD];
__device__ __nv_bfloat16 g_hh[MROWS * DD], g_hl[MROWS * DD];
__device__ __nv_bfloat16 g_qh[MROWS * DD], g_ql[MROWS * DD];
__device__ __nv_bfloat16 g_kh[MROWS * DD], g_kl[MROWS * DD];
__device__ __nv_bfloat16 g_vh[MROWS * DD], g_vl[MROWS * DD];
__device__ __nv_bfloat16 g_ctxh[MROWS * DD], g_ctxl[MROWS * DD];
__device__ __half g_h2[MROWS * DD];
__device__ __half g_mid[(size_t)MROWS * DFF];
__device__ __nv_bfloat16 g_wqh[DD * DD], g_wql[DD * DD];
__device__ __nv_bfloat16 g_wkh[DD * DD], g_wkl[DD * DD];
__device__ __nv_bfloat16 g_wvh[DD * DD], g_wvl[DD * DD];
__device__ __nv_bfloat16 g_woh[DD * DD], g_wol[DD * DD];
__device__ __half g_w1h[(size_t)DD * DFF], g_w1l[(size_t)DD * DFF];
__device__ __half g_w2h[(size_t)DFF * DD], g_w2l[(size_t)DFF * DD];

// ---------------- weight split kernels ----------------
__global__ void wsplit_bf16(const float* __restrict__ W, __nv_bfloat16* __restrict__ Th,
                            __nv_bfloat16* __restrict__ Tl, int K, int N) {
    __shared__ float tile[32][33];
    int bx = blockIdx.x, by = blockIdx.y, tx = threadIdx.x, ty = threadIdx.y;
    #pragma unroll
    for (int i = 0; i < 4; i++)
        tile[ty + 8 * i][tx] = W[(size_t)(by * 32 + ty + 8 * i) * N + bx * 32 + tx];
    __syncthreads();
    #pragma unroll
    for (int i = 0; i < 4; i++) {
        float v = tile[tx][ty + 8 * i];
        __nv_bfloat16 h = __float2bfloat16(v);
        __nv_bfloat16 l = __float2bfloat16(v - __bfloat162float(h));
        size_t o = (size_t)(bx * 32 + ty + 8 * i) * K + by * 32 + tx;
        Th[o] = h; Tl[o] = l;
    }
}
__global__ void wsplit_f16(const float* __restrict__ W, __half* __restrict__ Th,
                           __half* __restrict__ Tl, int K, int N) {
    __shared__ float tile[32][33];
    int bx = blockIdx.x, by = blockIdx.y, tx = threadIdx.x, ty = threadIdx.y;
    #pragma unroll
    for (int i = 0; i < 4; i++)
        tile[ty + 8 * i][tx] = W[(size_t)(by * 32 + ty + 8 * i) * N + bx * 32 + tx];
    __syncthreads();
    #pragma unroll
    for (int i = 0; i < 4; i++) {
        float v = tile[tx][ty + 8 * i];
        __half h = __float2half_rn(v);
        __half l = __float2half_rn(v - __half2float(h));
        size_t o = (size_t)(bx * 32 + ty + 8 * i) * K + by * 32 + tx;
        Th[o] = h; Tl[o] = l;
    }
}

// ---------------- LayerNorm ----------------
__device__ __forceinline__ void ln_core(const float* __restrict__ x,
                                        const float* __restrict__ gamma,
                                        const float* __restrict__ beta,
                                        int row, int tid, float* out4) {
    const float4 v = reinterpret_cast<const float4*>(x + (size_t)row * DD)[tid];
    float s = v.x + v.y + v.z + v.w;
    float sq = v.x * v.x + v.y * v.y + v.z * v.z + v.w * v.w;
    for (int o = 16; o > 0; o >>= 1) {
        s += __shfl_down_sync(0xffffffffu, s, o);
        sq += __shfl_down_sync(0xffffffffu, sq, o);
    }
    __shared__ float ws[8], wq[8];
    int lane = tid & 31, warp = tid >> 5;
    if (lane == 0) { ws[warp] = s; wq[warp] = sq; }
    __syncthreads();
    __shared__ float mu_s, rstd_s;
    if (tid == 0) {
        float ts = 0.f, tq = 0.f;
        #pragma unroll
        for (int i = 0; i < 8; i++) { ts += ws[i]; tq += wq[i]; }
        float mu = ts * (1.0f / DD);
        float var = tq * (1.0f / DD) - mu * mu;
        mu_s = mu; rstd_s = rsqrtf(var + 1e-5f);
    }
    __syncthreads();
    float mu = mu_s, r = rstd_s;
    float4 g4 = reinterpret_cast<const float4*>(gamma)[tid];
    float4 b4 = reinterpret_cast<const float4*>(beta)[tid];
    out4[0] = (v.x - mu) * r * g4.x + b4.x;
    out4[1] = (v.y - mu) * r * g4.y + b4.y;
    out4[2] = (v.z - mu) * r * g4.z + b4.z;
    out4[3] = (v.w - mu) * r * g4.w + b4.w;
}
__global__ void ln_bf16pair(const float* __restrict__ x, const float* __restrict__ g,
                            const float* __restrict__ b,
                            __nv_bfloat16* __restrict__ yh, __nv_bfloat16* __restrict__ yl) {
    int row = blockIdx.x, tid = threadIdx.x;
    float o[4];
    ln_core(x, g, b, row, tid, o);
    uint2 hw, lw;
    split2(o[0], o[1], hw.x, lw.x);
    split2(o[2], o[3], hw.y, lw.y);
    *reinterpret_cast<uint2*>(yh + (size_t)row * DD + tid * 4) = hw;
    *reinterpret_cast<uint2*>(yl + (size_t)row * DD + tid * 4) = lw;
}
__global__ void ln_f16(const float* __restrict__ x, const float* __restrict__ g,
                       const float* __restrict__ b, __half* __restrict__ y) {
    int row = blockIdx.x, tid = threadIdx.x;
    float o[4];
    ln_core(x, g, b, row, tid, o);
    __half2 h0 = __floats2half2_rn(o[0], o[1]);
    __half2 h1 = __floats2half2_rn(o[2], o[3]);
    uint2 w = make_uint2(*reinterpret_cast<const uint32_t*>(&h0),
                         *reinterpret_cast<const uint32_t*>(&h1));
    *reinterpret_cast<uint2*>(y + (size_t)row * DD + tid * 4) = w;
}

// ---------------- GEMM core ----------------
// TERMS=3 bf16: D = AhBh + AhBl + AlBh.  TERMS=2 fp16: D = A(Bh+Bl).
// mode 0: bf16 hi/lo out; 1: fp32 + bias + res; 2: fp16 + bias + gelu.
__device__ __forceinline__ void cpa_tile(uint32_t sdst, const uint16_t* __restrict__ g,
                                         int K, int r0, int k0, int tid) {
    #pragma unroll
    for (int l = 0; l < 4; l++) {
        int f = tid + 256 * l;
        int row = f >> 3, c = f & 7;
        CP_ASYNC16(sdst + swz(row, c * 16), g + (size_t)(r0 + row) * K + k0 + c * 8);
    }
}

template<int TERMS>
__device__ __forceinline__ void gemm_core(const uint16_t* __restrict__ A0,
                                          const uint16_t* __restrict__ A1,
                                          const uint16_t* __restrict__ B0,
                                          const uint16_t* __restrict__ B1,
                                          float* __restrict__ C,
                                          __nv_bfloat16* __restrict__ Ch,
                                          __nv_bfloat16* __restrict__ Cl,
                                          __half* __restrict__ Cf,
                                          int N, int K,
                                          const float* __restrict__ bias,
                                          const float* __restrict__ res, int mode) {
    constexpr uint32_t STAGE = (TERMS + 1) * 16384;
    extern __shared__ char smem[];
    const uint32_t sb0 = smem_to_u32(smem);
    const int tid = threadIdx.x;
    const int wid = tid >> 5, lane = tid & 31;
    const int wm = wid >> 2, wn = wid & 3;
    const int m0 = blockIdx.y * 128, n0 = blockIdx.x * 128;
    const int lr = lane & 15, lc = lane >> 4;

    float acc[4][4][4];
    #pragma unroll
    for (int i = 0; i < 4; i++)
        #pragma unroll
        for (int j = 0; j < 4; j++)
            #pragma unroll
            for (int p = 0; p < 4; p++) acc[i][j][p] = 0.f;

    const int T = K >> 6;
    auto load_tile = [&](int t, int s) {
        uint32_t sb = sb0 + s * STAGE;
        int k0 = t * 64;
        cpa_tile(sb, A0, K, m0, k0, tid);
        if (TERMS == 3) cpa_tile(sb + 16384, A1, K, m0, k0, tid);
        cpa_tile(sb + (TERMS == 3 ? 32768 : 16384), B0, K, n0, k0, tid);
        cpa_tile(sb + (TERMS == 3 ? 49152 : 32768), B1, K, n0, k0, tid);
    };

    load_tile(0, 0);
    CP_ASYNC_COMMIT();
    if (T > 1) load_tile(1, 1);
    CP_ASYNC_COMMIT();

    for (int t = 0; t < T; t++) {
        if (t + 2 < T) load_tile(t + 2, (t + 2) % 3);
        CP_ASYNC_COMMIT();
        CP_ASYNC_WAIT2();
        __syncthreads();

        const uint32_t sb = sb0 + (t % 3) * STAGE;
        const uint32_t sA0 = sb, sA1 = sb + 16384;
        const uint32_t sB0 = sb + (TERMS == 3 ? 32768 : 16384);
        const uint32_t sB1 = sb + (TERMS == 3 ? 49152 : 32768);
        #pragma unroll
        for (int kg = 0; kg < 4; kg++) {
            uint32_t a0[4][4], a1[4][4];
            #pragma unroll
            for (int mt = 0; mt < 4; mt++) {
                uint32_t off = swz(wm * 64 + mt * 16 + lr, kg * 32 + lc * 16);
                ldmx4(a0[mt], sA0 + off);
                if (TERMS == 3) ldmx4(a1[mt], sA1 + off);
            }
            uint32_t bh4[2][4], bl4[2][4];
            #pragma unroll
            for (int np = 0; np < 2; np++) {
                uint32_t off = swz(wn * 32 + np * 16 + lr, kg * 32 + lc * 16);
                ldmx4(bh4[np], sB0 + off);
                ldmx4(bl4[np], sB1 + off);
            }
            #pragma unroll
            for (int mt = 0; mt < 4; mt++) {
                #pragma unroll
                for (int nt = 0; nt < 4; nt++) {
                    int np = nt >> 1, u = nt & 1;
                    if (TERMS == 3) {
                        mma_bf16(acc[mt][nt], a0[mt], bh4[np][u], bh4[np][u + 2]);
                        mma_bf16(acc[mt][nt], a0[mt], bl4[np][u], bl4[np][u + 2]);
                        mma_bf16(acc[mt][nt], a1[mt], bh4[np][u], bh4[np][u + 2]);
                    } else {
                        mma_f16(acc[mt][nt], a0[mt], bh4[np][u], bh4[np][u + 2]);
                        mma_f16(acc[mt][nt], a0[mt], bl4[np][u], bl4[np][u + 2]);
                    }
                }
            }
        }
        __syncthreads();
    }

    #pragma unroll
    for (int mt = 0; mt < 4; mt++) {
        #pragma unroll
        for (int nt = 0; nt < 4; nt++) {
            int r0 = m0 + wm * 64 + mt * 16 + (lane >> 2);
            int c0 = n0 + wn * 32 + nt * 8 + (lane & 3) * 2;
            float bv0 = 0.f, bv1 = 0.f;
            if (mode != 0) { bv0 = bias[c0]; bv1 = bias[c0 + 1]; }
            #pragma unroll
            for (int half = 0; half < 2; half++) {
                int r = r0 + half * 8;
                float v0 = acc[mt][nt][half * 2 + 0] + bv0;
                float v1 = acc[mt][nt][half * 2 + 1] + bv1;
                if (mode == 0) {
                    uint32_t hw, lw;
                    split2(v0, v1, hw, lw);
                    *reinterpret_cast<uint32_t*>(Ch + (size_t)r * N + c0) = hw;
                    *reinterpret_cast<uint32_t*>(Cl + (size_t)r * N + c0) = lw;
                } else if (mode == 2) {
                    v0 = gelu_exact(v0); v1 = gelu_exact(v1);
                    __half2 hv = __floats2half2_rn(v0, v1);
                    *reinterpret_cast<uint32_t*>(Cf + (size_t)r * N + c0) =
                        *reinterpret_cast<const uint32_t*>(&hv);
                } else {
                    float2 rr = *(const float2*)(res + (size_t)r * N + c0);
                    *(float2*)(C + (size_t)r * N + c0) = make_float2(v0 + rr.x, v1 + rr.y);
                }
            }
        }
    }
}

#define GEMM3_SMEM (3 * 4 * 16384)
#define GEMM2_SMEM (3 * 3 * 16384)

__global__ void __launch_bounds__(256, 1)
gemm3_qkv(const __nv_bfloat16* __restrict__ Ah, const __nv_bfloat16* __restrict__ Al,
          const __nv_bfloat16* __restrict__ wqh, const __nv_bfloat16* __restrict__ wql,
          const __nv_bfloat16* __restrict__ wkh, const __nv_bfloat16* __restrict__ wkl,
          const __nv_bfloat16* __restrict__ wvh, const __nv_bfloat16* __restrict__ wvl,
          __nv_bfloat16* __restrict__ qh, __nv_bfloat16* __restrict__ ql,
          __nv_bfloat16* __restrict__ kh, __nv_bfloat16* __restrict__ kl,
          __nv_bfloat16* __restrict__ vh, __nv_bfloat16* __restrict__ vl) {
    const __nv_bfloat16* B0 = (blockIdx.z == 0) ? wqh : (blockIdx.z == 1) ? wkh : wvh;
    const __nv_bfloat16* B1 = (blockIdx.z == 0) ? wql : (blockIdx.z == 1) ? wkl : wvl;
    __nv_bfloat16* Ch = (blockIdx.z == 0) ? qh : (blockIdx.z == 1) ? kh : vh;
    __nv_bfloat16* Cl = (blockIdx.z == 0) ? ql : (blockIdx.z == 1) ? kl : vl;
    gemm_core<3>((const uint16_t*)Ah, (const uint16_t*)Al,
                 (const uint16_t*)B0, (const uint16_t*)B1,
                 nullptr, Ch, Cl, nullptr, DD, DD, nullptr, nullptr, 0);
}
__global__ void __launch_bounds__(256, 1)
gemm3_f32(const __nv_bfloat16* __restrict__ Ah, const __nv_bfloat16* __restrict__ Al,
          const __nv_bfloat16* __restrict__ B0, const __nv_bfloat16* __restrict__ B1,
          float* __restrict__ C, int N, int K,
          const float* __restrict__ bias, const float* __restrict__ res) {
    gemm_core<3>((const uint16_t*)Ah, (const uint16_t*)Al,
                 (const uint16_t*)B0, (const uint16_t*)B1,
                 C, nullptr, nullptr, nullptr, N, K, bias, res, 1);
}
__global__ void __launch_bounds__(256, 1)
gemm2_gelu(const __half* __restrict__ A,
           const __half* __restrict__ B0, const __half* __restrict__ B1,
           __half* __restrict__ Cf, int N, int K, const float* __restrict__ bias) {
    gemm_core<2>((const uint16_t*)A, nullptr, (const uint16_t*)B0, (const uint16_t*)B1,
                 nullptr, nullptr, nullptr, Cf, N, K, bias, nullptr, 2);
}
__global__ void __launch_bounds__(256, 1)
gemm2_f32(const __half* __restrict__ A,
          const __half* __restrict__ B0, const __half* __restrict__ B1,
          float* __restrict__ C, int N, int K,
          const float* __restrict__ bias, const float* __restrict__ res) {
    gemm_core<2>((const uint16_t*)A, nullptr, (const uint16_t*)B0, (const uint16_t*)B1,
                 C, nullptr, nullptr, nullptr, N, K, bias, res, 1);
}

// ---------------- Flash attention via mma.sync (bf16x2 3-term) ----------------
// CTA = (qt, b*16+h): 128 q-rows, 8 warps x 16 rows. KV tiles of 64, double-buffered.
// smem: Qh 16K | Ql 16K | 2 stages x {Kh,Kl,Vh,Vl 8K each}
#define AT_STAGE 32768
#define AT_SMEM (32768 + 2 * AT_STAGE)

__global__ void __launch_bounds__(256, 2)
attn_mma_kernel(const __nv_bfloat16* __restrict__ qh, const __nv_bfloat16* __restrict__ ql,
                const __nv_bfloat16* __restrict__ kh, const __nv_bfloat16* __restrict__ kl,
                const __nv_bfloat16* __restrict__ vh, const __nv_bfloat16* __restrict__ vl,
                __nv_bfloat16* __restrict__ Oh, __nv_bfloat16* __restrict__ Ol) {
    extern __shared__ char smem[];
    const uint32_t sb = smem_to_u32(smem);
    const uint32_t sQh = sb, sQl = sb + 16384;
    const int tid = threadIdx.x, wid = tid >> 5, lane = tid & 31;
    const int qt = blockIdx.x;
    const int h = blockIdx.y & 15, b = blockIdx.y >> 4;
    const size_t rowbase = (size_t)b * SS;
    const int colq = h * HDIM;

    #pragma unroll
    for (int l = 0; l < 4; l++) {
        int f = tid + 256 * l;
        int row = f >> 3, c = f & 7;
        size_t g = (rowbase + qt * 128 + row) * DD + colq + c * 8;
        uint32_t o = swz(row, c * 16);
        CP_ASYNC16(sQh + o, qh + g);
        CP_ASYNC16(sQl + o, ql + g);
    }
    CP_ASYNC_COMMIT();

    auto load_kv = [&](int kt, int s) {
        uint32_t st = sb + 32768 + s * AT_STAGE;
        #pragma unroll
        for (int l = 0; l < 2; l++) {
            int f = tid + 256 * l;
            int row = f >> 3, c = f & 7;
            size_t g = (rowbase + kt * 64 + row) * DD + colq + c * 8;
            uint32_t o = swz(row, c * 16);
            CP_ASYNC16(st + o,         kh + g);
            CP_ASYNC16(st + 8192 + o,  kl + g);
            CP_ASYNC16(st + 16384 + o, vh + g);
            CP_ASYNC16(st + 24576 + o, vl + g);
        }
    };
    load_kv(0, 0);
    CP_ASYNC_COMMIT();

    const int nkt = 2 * qt + 2;
    const int ktmax_w = (qt * 128 + wid * 16 + 15) >> 6;
    const int lr = lane & 15, lc = lane >> 4;
    const int r0l = lane >> 2;
    const int c2 = (lane & 3) * 2;
    const int rowg0 = qt * 128 + wid * 16 + r0l;

    float m_i[2] = {-1e30f, -1e30f}, l_i[2] = {0.f, 0.f};
    float oacc[8][4];
    #pragma unroll
    for (int i = 0; i < 8; i++)
        #pragma unroll
        for (int j = 0; j < 4; j++) oacc[i][j] = 0.f;

    for (int kt = 0; kt < nkt; kt++) {
        if (kt + 1 < nkt) load_kv(kt + 1, (kt + 1) & 1);
        CP_ASYNC_COMMIT();
        CP_ASYNC_WAIT1();
        __syncthreads();

        if (kt <= ktmax_w) {
            uint32_t st = sb + 32768 + (kt & 1) * AT_STAGE;
            uint32_t sKh = st, sKl = st + 8192, sVh = st + 16384, sVl = st + 24576;

            float sacc[8][4];
            #pragma unroll
            for (int i = 0; i < 8; i++)
                #pragma unroll
                for (int j = 0; j < 4; j++) sacc[i][j] = 0.f;

            #pragma unroll
            for (int kg = 0; kg < 4; kg++) {
                uint32_t a0[4], a1[4];
                uint32_t aoff = swz(wid * 16 + lr, kg * 32 + lc * 16);
                ldmx4(a0, sQh + aoff);
                ldmx4(a1, sQl + aoff);
                #pragma unroll
                for (int np = 0; np < 4; np++) {
                    uint32_t bh4[4], bl4[4];
                    uint32_t boff = swz(np * 16 + lr, kg * 32 + lc * 16);
                    ldmx4(bh4, sKh + boff);
                    ldmx4(bl4, sKl + boff);
                    #pragma unroll
                    for (int u = 0; u < 2; u++) {
                        int nt = np * 2 + u;
                        mma_bf16(sacc[nt], a0, bh4[u], bh4[u + 2]);
                        mma_bf16(sacc[nt], a0, bl4[u], bl4[u + 2]);
                        mma_bf16(sacc[nt], a1, bh4[u], bh4[u + 2]);
                    }
                }
            }

            float rm[2] = {-1e30f, -1e30f};
            #pragma unroll
            for (int nt = 0; nt < 8; nt++) {
                #pragma unroll
                for (int j = 0; j < 4; j++) {
                    int jr = j >> 1;
                    int rowg = rowg0 + jr * 8;
                    int colg = kt * 64 + nt * 8 + c2 + (j & 1);
                    float s = sacc[nt][j] * 0.125f;
                    if (colg > rowg) s = -1e30f;
                    sacc[nt][j] = s;
                    rm[jr] = fmaxf(rm[jr], s);
                }
            }
            #pragma unroll
            for (int jr = 0; jr < 2; jr++) {
                rm[jr] = fmaxf(rm[jr], __shfl_xor_sync(0xffffffffu, rm[jr], 1));
                rm[jr] = fmaxf(rm[jr], __shfl_xor_sync(0xffffffffu, rm[jr], 2));
            }
            float sc[2], rs[2] = {0.f, 0.f};
            #pragma unroll
            for (int jr = 0; jr < 2; jr++) {
                float mn = fmaxf(m_i[jr], rm[jr]);
                sc[jr] = __expf(m_i[jr] - mn);
                m_i[jr] = mn;
            }
            #pragma unroll
            for (int nt = 0; nt < 8; nt++) {
                #pragma unroll
                for (int j = 0; j < 4; j++) {
                    float p = __expf(sacc[nt][j] - m_i[j >> 1]);
                    sacc[nt][j] = p;
                    rs[j >> 1] += p;
                }
            }
            #pragma unroll
            for (int jr = 0; jr < 2; jr++) {
                rs[jr] += __shfl_xor_sync(0xffffffffu, rs[jr], 1);
                rs[jr] += __shfl_xor_sync(0xffffffffu, rs[jr], 2);
                l_i[jr] = l_i[jr] * sc[jr] + rs[jr];
            }
            #pragma unroll
            for (int nt = 0; nt < 8; nt++) {
                #pragma unroll
                for (int j = 0; j < 4; j++) oacc[nt][j] *= sc[j >> 1];
            }

            #pragma unroll
            for (int kc = 0; kc < 4; kc++) {
                uint32_t ph[4], pl[4];
                split2(sacc[2 * kc][0],     sacc[2 * kc][1],     ph[0], pl[0]);
                split2(sacc[2 * kc][2],     sacc[2 * kc][3],     ph[1], pl[1]);
                split2(sacc[2 * kc + 1][0], sacc[2 * kc + 1][1], ph[2], pl[2]);
                split2(sacc[2 * kc + 1][2], sacc[2 * kc + 1][3], ph[3], pl[3]);
                uint32_t vrow = kc * 16 + ((lane >> 3) & 1) * 8 + (lane & 7);
                #pragma unroll
                for (int dp = 0; dp < 4; dp++) {
                    uint32_t vh4[4], vl4[4];
                    uint32_t voff = swz(vrow, dp * 32 + (lane >> 4) * 16);
                    ldmx4t(vh4, sVh + voff);
                    ldmx4t(vl4, sVl + voff);
                    mma_bf16(oacc[dp * 2],     ph, vh4[0], vh4[1]);
                    mma_bf16(oacc[dp * 2],     ph, vl4[0], vl4[1]);
                    mma_bf16(oacc[dp * 2],     pl, vh4[0], vh4[1]);
                    mma_bf16(oacc[dp * 2 + 1], ph, vh4[2], vh4[3]);
                    mma_bf16(oacc[dp * 2 + 1], ph, vl4[2], vl4[3]);
                    mma_bf16(oacc[dp * 2 + 1], pl, vh4[2], vh4[3]);
                }
            }
        }
        __syncthreads();
    }

    float inv[2] = {1.0f / l_i[0], 1.0f / l_i[1]};
    #pragma unroll
    for (int nt = 0; nt < 8; nt++) {
        #pragma unroll
        for (int jr = 0; jr < 2; jr++) {
            float v0 = oacc[nt][jr * 2 + 0] * inv[jr];
            float v1 = oacc[nt][jr * 2 + 1] * inv[jr];
            uint32_t hw, lw;
            split2(v0, v1, hw, lw);
            size_t off = (rowbase + rowg0 + jr * 8) * DD + colq + nt * 8 + c2;
            *reinterpret_cast<uint32_t*>(Oh + off) = hw;
            *reinterpret_cast<uint32_t*>(Ol + off) = lw;
        }
    }
}

// ---------------- launch ----------------
extern "C" void kernel_launch(void* const* d_in, const int* in_sizes, int n_in,
                              void* d_out, int out_size) {
    const float* x     = (const float*)d_in[0];
    const float* ln1_g = (const float*)d_in[1];
    const float* ln1_b = (const float*)d_in[2];
    const float* Wq    = (const float*)d_in[3];
    const float* Wk    = (const float*)d_in[4];
    const float* Wv    = (const float*)d_in[5];
    const float* Wo    = (const float*)d_in[6];
    const float* bo    = (const float*)d_in[7];
    const float* ln2_g = (const float*)d_in[8];
    const float* ln2_b = (const float*)d_in[9];
    const float* W1    = (const float*)d_in[10];
    const float* b1    = (const float*)d_in[11];
    const float* W2    = (const float*)d_in[12];
    const float* b2    = (const float*)d_in[13];
    float* out = (float*)d_out;

    float* x2;
    cudaGetSymbolAddress((void**)&x2, g_x2);
    __nv_bfloat16 *hh, *hl, *qh, *ql, *kh, *kl, *vh, *vl, *ctxh, *ctxl;
    cudaGetSymbolAddress((void**)&hh, g_hh);     cudaGetSymbolAddress((void**)&hl, g_hl);
    cudaGetSymbolAddress((void**)&qh, g_qh);     cudaGetSymbolAddress((void**)&ql, g_ql);
    cudaGetSymbolAddress((void**)&kh, g_kh);     cudaGetSymbolAddress((void**)&kl, g_kl);
    cudaGetSymbolAddress((void**)&vh, g_vh);     cudaGetSymbolAddress((void**)&vl, g_vl);
    cudaGetSymbolAddress((void**)&ctxh, g_ctxh); cudaGetSymbolAddress((void**)&ctxl, g_ctxl);
    __half *h2, *mid;
    cudaGetSymbolAddress((void**)&h2, g_h2);     cudaGetSymbolAddress((void**)&mid, g_mid);

    __nv_bfloat16 *wqh, *wql, *wkh, *wkl, *wvh, *wvl, *woh, *wol;
    cudaGetSymbolAddress((void**)&wqh, g_wqh); cudaGetSymbolAddress((void**)&wql, g_wql);
    cudaGetSymbolAddress((void**)&wkh, g_wkh); cudaGetSymbolAddress((void**)&wkl, g_wkl);
    cudaGetSymbolAddress((void**)&wvh, g_wvh); cudaGetSymbolAddress((void**)&wvl, g_wvl);
    cudaGetSymbolAddress((void**)&woh, g_woh); cudaGetSymbolAddress((void**)&wol, g_wol);
    __half *w1h, *w1l, *w2h, *w2l;
    cudaGetSymbolAddress((void**)&w1h, g_w1h); cudaGetSymbolAddress((void**)&w1l, g_w1l);
    cudaGetSymbolAddress((void**)&w2h, g_w2h); cudaGetSymbolAddress((void**)&w2l, g_w2l);

    static int attr_set = 0;
    if (!attr_set) {
        cudaFuncSetAttribute(attn_mma_kernel, cudaFuncAttributeMaxDynamicSharedMemorySize, AT_SMEM);
        cudaFuncSetAttribute(gemm3_qkv,  cudaFuncAttributeMaxDynamicSharedMemorySize, GEMM3_SMEM);
        cudaFuncSetAttribute(gemm3_f32,  cudaFuncAttributeMaxDynamicSharedMemorySize, GEMM3_SMEM);
        cudaFuncSetAttribute(gemm2_gelu, cudaFuncAttributeMaxDynamicSharedMemorySize, GEMM2_SMEM);
        cudaFuncSetAttribute(gemm2_f32,  cudaFuncAttributeMaxDynamicSharedMemorySize, GEMM2_SMEM);
        attr_set = 1;
    }

    const int M = MROWS;
    dim3 tb(32, 8);

    wsplit_bf16<<<dim3(DD / 32, DD / 32), tb>>>(Wq, wqh, wql, DD, DD);
    wsplit_bf16<<<dim3(DD / 32, DD / 32), tb>>>(Wk, wkh, wkl, DD, DD);
    wsplit_bf16<<<dim3(DD / 32, DD / 32), tb>>>(Wv, wvh, wvl, DD, DD);
    wsplit_bf16<<<dim3(DD / 32, DD / 32), tb>>>(Wo, woh, wol, DD, DD);
    wsplit_f16 <<<dim3(DFF / 32, DD / 32), tb>>>(W1, w1h, w1l, DD, DFF);
    wsplit_f16 <<<dim3(DD / 32, DFF / 32), tb>>>(W2, w2h, w2l, DFF, DD);

    ln_bf16pair<<<M, 256>>>(x, ln1_g, ln1_b, hh, hl);

    dim3 gQKV(DD / 128, M / 128, 3);
    gemm3_qkv<<<gQKV, 256, GEMM3_SMEM>>>(hh, hl, wqh, wql, wkh, wkl, wvh, wvl,
                                         qh, ql, kh, kl, vh, vl);

    dim3 gA(SS / 128, BB * HH);
    attn_mma_kernel<<<gA, 256, AT_SMEM>>>(qh, ql, kh, kl, vh, vl, ctxh, ctxl);

    dim3 gDD(DD / 128, M / 128);
    gemm3_f32<<<gDD, 256, GEMM3_SMEM>>>(ctxh, ctxl, woh, wol, x2, DD, DD, bo, x);

    ln_f16<<<M, 256>>>(x2, ln2_g, ln2_b, h2);

    dim3 gFF(DFF / 128, M / 128);
    gemm2_gelu<<<gFF, 256, GEMM2_SMEM>>>(h2, w1h, w1l, mid, DFF, DD, b1);

    gemm2_f32<<<gDD, 256, GEMM2_SMEM>>>(mid, w2h, w2l, out, DD, DFF, b2, x2);
}

// round 8
// speedup vs baseline: 1.7165x; 1.6340x over previous
#include <cuda_runtime.h>
#include <cuda_bf16.h>
#include <cuda_fp16.h>
#include <math.h>
#include <cstdint>

#define BB 2
#define SS 2048
#define DD 1024
#define HH 16
#define HDIM 64
#define DFF 4096
#define MROWS (BB * SS)

// ---------------- PTX helpers ----------------
__device__ __forceinline__ uint32_t smem_to_u32(const void* p) {
    uint32_t a;
    asm("{ .reg .u64 t; cvta.to.shared.u64 t, %1; cvt.u32.u64 %0, t; }" : "=r"(a) : "l"(p));
    return a;
}
__device__ __forceinline__ void ldmx4(uint32_t* r, uint32_t a) {
    asm volatile("ldmatrix.sync.aligned.m8n8.x4.shared.b16 {%0,%1,%2,%3}, [%4];"
        : "=r"(r[0]), "=r"(r[1]), "=r"(r[2]), "=r"(r[3]) : "r"(a));
}
__device__ __forceinline__ void ldmx4t(uint32_t* r, uint32_t a) {
    asm volatile("ldmatrix.sync.aligned.m8n8.x4.trans.shared.b16 {%0,%1,%2,%3}, [%4];"
        : "=r"(r[0]), "=r"(r[1]), "=r"(r[2]), "=r"(r[3]) : "r"(a));
}
__device__ __forceinline__ void mma_bf16(float* c, const uint32_t* a, uint32_t b0, uint32_t b1) {
    asm volatile("mma.sync.aligned.m16n8k16.row.col.f32.bf16.bf16.f32 "
        "{%0,%1,%2,%3}, {%4,%5,%6,%7}, {%8,%9}, {%0,%1,%2,%3};"
        : "+f"(c[0]), "+f"(c[1]), "+f"(c[2]), "+f"(c[3])
        : "r"(a[0]), "r"(a[1]), "r"(a[2]), "r"(a[3]), "r"(b0), "r"(b1));
}
__device__ __forceinline__ void mma_f16(float* c, const uint32_t* a, uint32_t b0, uint32_t b1) {
    asm volatile("mma.sync.aligned.m16n8k16.row.col.f32.f16.f16.f32 "
        "{%0,%1,%2,%3}, {%4,%5,%6,%7}, {%8,%9}, {%0,%1,%2,%3};"
        : "+f"(c[0]), "+f"(c[1]), "+f"(c[2]), "+f"(c[3])
        : "r"(a[0]), "r"(a[1]), "r"(a[2]), "r"(a[3]), "r"(b0), "r"(b1));
}
#define CP_ASYNC16(s, g) asm volatile("cp.async.cg.shared.global [%0], [%1], 16;" :: "r"(s), "l"(g))
#define CP_ASYNC_COMMIT() asm volatile("cp.async.commit_group;" ::: "memory")
#define CP_ASYNC_WAIT2()  asm volatile("cp.async.wait_group 2;" ::: "memory")
#define CP_ASYNC_WAIT1()  asm volatile("cp.async.wait_group 1;" ::: "memory")

__device__ __forceinline__ uint32_t swz(uint32_t row, uint32_t colbyte) {
    return row * 128 + (colbyte ^ ((row & 7) << 4));
}
__device__ __forceinline__ void split2(float a, float b, uint32_t& hw, uint32_t& lw) {
    __nv_bfloat162 h = __floats2bfloat162_rn(a, b);
    float2 f = __bfloat1622float2(h);
    __nv_bfloat162 l = __floats2bfloat162_rn(a - f.x, b - f.y);
    hw = *reinterpret_cast<const uint32_t*>(&h);
    lw = *reinterpret_cast<const uint32_t*>(&l);
}
__device__ __forceinline__ void split2h(float a, float b, uint32_t& hw, uint32_t& lw) {
    __half2 h = __floats2half2_rn(a, b);
    float2 f = __half22float2(h);
    __half2 l = __floats2half2_rn(a - f.x, b - f.y);
    hw = *reinterpret_cast<const uint32_t*>(&h);
    lw = *reinterpret_cast<const uint32_t*>(&l);
}
__device__ __forceinline__ float gelu_exact(float v) {
    return 0.5f * v * (1.0f + erff(v * 0.70710678118654752f));
}

// ---------------- scratch ----------------
__device__ float g_x2[MROWS * DD];
__device__ __nv_bfloat16 g_hh[MROWS * DD], g_hl[MROWS * DD];
__device__ __half g_qh[MROWS * DD];                        // Q fp16 (single)
__device__ __half g_kh[MROWS * DD], g_kl[MROWS * DD];      // K fp16 pair
__device__ __half g_vh[MROWS * DD];                        // V fp16 (single)
__device__ __nv_bfloat16 g_ctxh[MROWS * DD], g_ctxl[MROWS * DD];
__device__ __half g_h2[MROWS * DD];
__device__ __half g_mid[(size_t)MROWS * DFF];
__device__ __nv_bfloat16 g_wqh[DD * DD], g_wql[DD * DD];
__device__ __nv_bfloat16 g_wkh[DD * DD], g_wkl[DD * DD];
__device__ __nv_bfloat16 g_wvh[DD * DD], g_wvl[DD * DD];
__device__ __nv_bfloat16 g_woh[DD * DD], g_wol[DD * DD];
__device__ __half g_w1h[(size_t)DD * DFF], g_w1l[(size_t)DD * DFF];
__device__ __half g_w2h[(size_t)DFF * DD], g_w2l[(size_t)DFF * DD];

// ---------------- weight split kernels ----------------
__global__ void wsplit_bf16(const float* __restrict__ W, __nv_bfloat16* __restrict__ Th,
                            __nv_bfloat16* __restrict__ Tl, int K, int N) {
    __shared__ float tile[32][33];
    int bx = blockIdx.x, by = blockIdx.y, tx = threadIdx.x, ty = threadIdx.y;
    #pragma unroll
    for (int i = 0; i < 4; i++)
        tile[ty + 8 * i][tx] = W[(size_t)(by * 32 + ty + 8 * i) * N + bx * 32 + tx];
    __syncthreads();
    #pragma unroll
    for (int i = 0; i < 4; i++) {
        float v = tile[tx][ty + 8 * i];
        __nv_bfloat16 h = __float2bfloat16(v);
        __nv_bfloat16 l = __float2bfloat16(v - __bfloat162float(h));
        size_t o = (size_t)(bx * 32 + ty + 8 * i) * K + by * 32 + tx;
        Th[o] = h; Tl[o] = l;
    }
}
__global__ void wsplit_f16(const float* __restrict__ W, __half* __restrict__ Th,
                           __half* __restrict__ Tl, int K, int N) {
    __shared__ float tile[32][33];
    int bx = blockIdx.x, by = blockIdx.y, tx = threadIdx.x, ty = threadIdx.y;
    #pragma unroll
    for (int i = 0; i < 4; i++)
        tile[ty + 8 * i][tx] = W[(size_t)(by * 32 + ty + 8 * i) * N + bx * 32 + tx];
    __syncthreads();
    #pragma unroll
    for (int i = 0; i < 4; i++) {
        float v = tile[tx][ty + 8 * i];
        __half h = __float2half_rn(v);
        __half l = __float2half_rn(v - __half2float(h));
        size_t o = (size_t)(bx * 32 + ty + 8 * i) * K + by * 32 + tx;
        Th[o] = h; Tl[o] = l;
    }
}

// ---------------- LayerNorm ----------------
__device__ __forceinline__ void ln_core(const float* __restrict__ x,
                                        const float* __restrict__ gamma,
                                        const float* __restrict__ beta,
                                        int row, int tid, float* out4) {
    const float4 v = reinterpret_cast<const float4*>(x + (size_t)row * DD)[tid];
    float s = v.x + v.y + v.z + v.w;
    float sq = v.x * v.x + v.y * v.y + v.z * v.z + v.w * v.w;
    for (int o = 16; o > 0; o >>= 1) {
        s += __shfl_down_sync(0xffffffffu, s, o);
        sq += __shfl_down_sync(0xffffffffu, sq, o);
    }
    __shared__ float ws[8], wq[8];
    int lane = tid & 31, warp = tid >> 5;
    if (lane == 0) { ws[warp] = s; wq[warp] = sq; }
    __syncthreads();
    __shared__ float mu_s, rstd_s;
    if (tid == 0) {
        float ts = 0.f, tq = 0.f;
        #pragma unroll
        for (int i = 0; i < 8; i++) { ts += ws[i]; tq += wq[i]; }
        float mu = ts * (1.0f / DD);
        float var = tq * (1.0f / DD) - mu * mu;
        mu_s = mu; rstd_s = rsqrtf(var + 1e-5f);
    }
    __syncthreads();
    float mu = mu_s, r = rstd_s;
    float4 g4 = reinterpret_cast<const float4*>(gamma)[tid];
    float4 b4 = reinterpret_cast<const float4*>(beta)[tid];
    out4[0] = (v.x - mu) * r * g4.x + b4.x;
    out4[1] = (v.y - mu) * r * g4.y + b4.y;
    out4[2] = (v.z - mu) * r * g4.z + b4.z;
    out4[3] = (v.w - mu) * r * g4.w + b4.w;
}
__global__ void ln_bf16pair(const float* __restrict__ x, const float* __restrict__ g,
                            const float* __restrict__ b,
                            __nv_bfloat16* __restrict__ yh, __nv_bfloat16* __restrict__ yl) {
    int row = blockIdx.x, tid = threadIdx.x;
    float o[4];
    ln_core(x, g, b, row, tid, o);
    uint2 hw, lw;
    split2(o[0], o[1], hw.x, lw.x);
    split2(o[2], o[3], hw.y, lw.y);
    *reinterpret_cast<uint2*>(yh + (size_t)row * DD + tid * 4) = hw;
    *reinterpret_cast<uint2*>(yl + (size_t)row * DD + tid * 4) = lw;
}
__global__ void ln_f16(const float* __restrict__ x, const float* __restrict__ g,
                       const float* __restrict__ b, __half* __restrict__ y) {
    int row = blockIdx.x, tid = threadIdx.x;
    float o[4];
    ln_core(x, g, b, row, tid, o);
    __half2 h0 = __floats2half2_rn(o[0], o[1]);
    __half2 h1 = __floats2half2_rn(o[2], o[3]);
    uint2 w = make_uint2(*reinterpret_cast<const uint32_t*>(&h0),
                         *reinterpret_cast<const uint32_t*>(&h1));
    *reinterpret_cast<uint2*>(y + (size_t)row * DD + tid * 4) = w;
}

// ---------------- GEMM core ----------------
// TERMS=3 bf16: D = AhBh + AhBl + AlBh.  TERMS=2 fp16: D = A(Bh+Bl).
// mode 0: bf16 pair out; 1: fp32+bias+res; 2: fp16+bias+gelu; 3: fp16 pair out
__device__ __forceinline__ void cpa_tile(uint32_t sdst, const uint16_t* __restrict__ g,
                                         int K, int r0, int k0, int tid) {
    #pragma unroll
    for (int l = 0; l < 4; l++) {
        int f = tid + 256 * l;
        int row = f >> 3, c = f & 7;
        CP_ASYNC16(sdst + swz(row, c * 16), g + (size_t)(r0 + row) * K + k0 + c * 8);
    }
}

template<int TERMS>
__device__ __forceinline__ void gemm_core(const uint16_t* __restrict__ A0,
                                          const uint16_t* __restrict__ A1,
                                          const uint16_t* __restrict__ B0,
                                          const uint16_t* __restrict__ B1,
                                          float* __restrict__ C,
                                          uint16_t* __restrict__ Ch,
                                          uint16_t* __restrict__ Cl,
                                          __half* __restrict__ Cf,
                                          int N, int K,
                                          const float* __restrict__ bias,
                                          const float* __restrict__ res, int mode) {
    constexpr uint32_t STAGE = (TERMS + 1) * 16384;
    extern __shared__ char smem[];
    const uint32_t sb0 = smem_to_u32(smem);
    const int tid = threadIdx.x;
    const int wid = tid >> 5, lane = tid & 31;
    const int wm = wid >> 2, wn = wid & 3;
    const int m0 = blockIdx.y * 128, n0 = blockIdx.x * 128;
    const int lr = lane & 15, lc = lane >> 4;

    float acc[4][4][4];
    #pragma unroll
    for (int i = 0; i < 4; i++)
        #pragma unroll
        for (int j = 0; j < 4; j++)
            #pragma unroll
            for (int p = 0; p < 4; p++) acc[i][j][p] = 0.f;

    const int T = K >> 6;
    auto load_tile = [&](int t, int s) {
        uint32_t sb = sb0 + s * STAGE;
        int k0 = t * 64;
        cpa_tile(sb, A0, K, m0, k0, tid);
        if (TERMS == 3) cpa_tile(sb + 16384, A1, K, m0, k0, tid);
        cpa_tile(sb + (TERMS == 3 ? 32768 : 16384), B0, K, n0, k0, tid);
        cpa_tile(sb + (TERMS == 3 ? 49152 : 32768), B1, K, n0, k0, tid);
    };

    load_tile(0, 0);
    CP_ASYNC_COMMIT();
    if (T > 1) load_tile(1, 1);
    CP_ASYNC_COMMIT();

    for (int t = 0; t < T; t++) {
        if (t + 2 < T) load_tile(t + 2, (t + 2) % 3);
        CP_ASYNC_COMMIT();
        CP_ASYNC_WAIT2();
        __syncthreads();

        const uint32_t sb = sb0 + (t % 3) * STAGE;
        const uint32_t sA0 = sb, sA1 = sb + 16384;
        const uint32_t sB0 = sb + (TERMS == 3 ? 32768 : 16384);
        const uint32_t sB1 = sb + (TERMS == 3 ? 49152 : 32768);
        #pragma unroll
        for (int kg = 0; kg < 4; kg++) {
            uint32_t a0[4][4], a1[4][4];
            #pragma unroll
            for (int mt = 0; mt < 4; mt++) {
                uint32_t off = swz(wm * 64 + mt * 16 + lr, kg * 32 + lc * 16);
                ldmx4(a0[mt], sA0 + off);
                if (TERMS == 3) ldmx4(a1[mt], sA1 + off);
            }
            uint32_t bh4[2][4], bl4[2][4];
            #pragma unroll
            for (int np = 0; np < 2; np++) {
                uint32_t off = swz(wn * 32 + np * 16 + lr, kg * 32 + lc * 16);
                ldmx4(bh4[np], sB0 + off);
                ldmx4(bl4[np], sB1 + off);
            }
            #pragma unroll
            for (int mt = 0; mt < 4; mt++) {
                #pragma unroll
                for (int nt = 0; nt < 4; nt++) {
                    int np = nt >> 1, u = nt & 1;
                    if (TERMS == 3) {
                        mma_bf16(acc[mt][nt], a0[mt], bh4[np][u], bh4[np][u + 2]);
                        mma_bf16(acc[mt][nt], a0[mt], bl4[np][u], bl4[np][u + 2]);
                        mma_bf16(acc[mt][nt], a1[mt], bh4[np][u], bh4[np][u + 2]);
                    } else {
                        mma_f16(acc[mt][nt], a0[mt], bh4[np][u], bh4[np][u + 2]);
                        mma_f16(acc[mt][nt], a0[mt], bl4[np][u], bl4[np][u + 2]);
                    }
                }
            }
        }
        __syncthreads();
    }

    #pragma unroll
    for (int mt = 0; mt < 4; mt++) {
        #pragma unroll
        for (int nt = 0; nt < 4; nt++) {
            int r0 = m0 + wm * 64 + mt * 16 + (lane >> 2);
            int c0 = n0 + wn * 32 + nt * 8 + (lane & 3) * 2;
            float bv0 = 0.f, bv1 = 0.f;
            if (mode == 1 || mode == 2) { bv0 = bias[c0]; bv1 = bias[c0 + 1]; }
            #pragma unroll
            for (int half = 0; half < 2; half++) {
                int r = r0 + half * 8;
                float v0 = acc[mt][nt][half * 2 + 0] + bv0;
                float v1 = acc[mt][nt][half * 2 + 1] + bv1;
                if (mode == 0) {
                    uint32_t hw, lw;
                    split2(v0, v1, hw, lw);
                    *reinterpret_cast<uint32_t*>(Ch + (size_t)r * N + c0) = hw;
                    *reinterpret_cast<uint32_t*>(Cl + (size_t)r * N + c0) = lw;
                } else if (mode == 3) {
                    uint32_t hw, lw;
                    split2h(v0, v1, hw, lw);
                    *reinterpret_cast<uint32_t*>(Ch + (size_t)r * N + c0) = hw;
                    if (Cl) *reinterpret_cast<uint32_t*>(Cl + (size_t)r * N + c0) = lw;
                } else if (mode == 2) {
                    v0 = gelu_exact(v0); v1 = gelu_exact(v1);
                    __half2 hv = __floats2half2_rn(v0, v1);
                    *reinterpret_cast<uint32_t*>(Cf + (size_t)r * N + c0) =
                        *reinterpret_cast<const uint32_t*>(&hv);
                } else {
                    float2 rr = *(const float2*)(res + (size_t)r * N + c0);
                    *(float2*)(C + (size_t)r * N + c0) = make_float2(v0 + rr.x, v1 + rr.y);
                }
            }
        }
    }
}

#define GEMM3_SMEM (3 * 4 * 16384)
#define GEMM2_SMEM (3 * 3 * 16384)

__global__ void __launch_bounds__(256, 1)
gemm3_qkv(const __nv_bfloat16* __restrict__ Ah, const __nv_bfloat16* __restrict__ Al,
          const __nv_bfloat16* __restrict__ wqh, const __nv_bfloat16* __restrict__ wql,
          const __nv_bfloat16* __restrict__ wkh, const __nv_bfloat16* __restrict__ wkl,
          const __nv_bfloat16* __restrict__ wvh, const __nv_bfloat16* __restrict__ wvl,
          __half* __restrict__ qh, __half* __restrict__ kh, __half* __restrict__ kl,
          __half* __restrict__ vh) {
    const __nv_bfloat16* B0 = (blockIdx.z == 0) ? wqh : (blockIdx.z == 1) ? wkh : wvh;
    const __nv_bfloat16* B1 = (blockIdx.z == 0) ? wql : (blockIdx.z == 1) ? wkl : wvl;
    uint16_t* Ch = (uint16_t*)((blockIdx.z == 0) ? qh : (blockIdx.z == 1) ? kh : vh);
    uint16_t* Cl = (blockIdx.z == 1) ? (uint16_t*)kl : nullptr;
    gemm_core<3>((const uint16_t*)Ah, (const uint16_t*)Al,
                 (const uint16_t*)B0, (const uint16_t*)B1,
                 nullptr, Ch, Cl, nullptr, DD, DD, nullptr, nullptr, 3);
}
__global__ void __launch_bounds__(256, 1)
gemm3_f32(const __nv_bfloat16* __restrict__ Ah, const __nv_bfloat16* __restrict__ Al,
          const __nv_bfloat16* __restrict__ B0, const __nv_bfloat16* __restrict__ B1,
          float* __restrict__ C, int N, int K,
          const float* __restrict__ bias, const float* __restrict__ res) {
    gemm_core<3>((const uint16_t*)Ah, (const uint16_t*)Al,
                 (const uint16_t*)B0, (const uint16_t*)B1,
                 C, nullptr, nullptr, nullptr, N, K, bias, res, 1);
}
__global__ void __launch_bounds__(256, 1)
gemm2_gelu(const __half* __restrict__ A,
           const __half* __restrict__ B0, const __half* __restrict__ B1,
           __half* __restrict__ Cf, int N, int K, const float* __restrict__ bias) {
    gemm_core<2>((const uint16_t*)A, nullptr, (const uint16_t*)B0, (const uint16_t*)B1,
                 nullptr, nullptr, nullptr, Cf, N, K, bias, nullptr, 2);
}
__global__ void __launch_bounds__(256, 1)
gemm2_f32(const __half* __restrict__ A,
          const __half* __restrict__ B0, const __half* __restrict__ B1,
          float* __restrict__ C, int N, int K,
          const float* __restrict__ bias, const float* __restrict__ res) {
    gemm_core<2>((const uint16_t*)A, nullptr, (const uint16_t*)B0, (const uint16_t*)B1,
                 C, nullptr, nullptr, nullptr, N, K, bias, res, 1);
}

// ---------------- Flash attention fp16 2-term ----------------
// S = Q(fp16) @ (Kh+Kl)^T ; O = (Ph+Pl) @ V(fp16).
// CTA = (qt, b*16+h): 128 q-rows, 8 warps x 16 rows. KV tiles of 64, double-buffered.
// smem: Q 16K | 2 stages x {Kh 8K, Kl 8K, V 8K}
#define AT_STAGE 24576
#define AT_SMEM (16384 + 2 * AT_STAGE)

__global__ void __launch_bounds__(256, 2)
attn_mma_kernel(const __half* __restrict__ q, const __half* __restrict__ kh,
                const __half* __restrict__ kl, const __half* __restrict__ v,
                __nv_bfloat16* __restrict__ Oh, __nv_bfloat16* __restrict__ Ol) {
    extern __shared__ char smem[];
    const uint32_t sb = smem_to_u32(smem);
    const uint32_t sQ = sb;
    const int tid = threadIdx.x, wid = tid >> 5, lane = tid & 31;
    const int qt = blockIdx.x;
    const int h = blockIdx.y & 15, b = blockIdx.y >> 4;
    const size_t rowbase = (size_t)b * SS;
    const int colq = h * HDIM;

    #pragma unroll
    for (int l = 0; l < 4; l++) {
        int f = tid + 256 * l;
        int row = f >> 3, c = f & 7;
        CP_ASYNC16(sQ + swz(row, c * 16),
                   q + (rowbase + qt * 128 + row) * DD + colq + c * 8);
    }
    CP_ASYNC_COMMIT();

    auto load_kv = [&](int kt, int s) {
        uint32_t st = sb + 16384 + s * AT_STAGE;
        #pragma unroll
        for (int l = 0; l < 2; l++) {
            int f = tid + 256 * l;
            int row = f >> 3, c = f & 7;
            size_t g = (rowbase + kt * 64 + row) * DD + colq + c * 8;
            uint32_t o = swz(row, c * 16);
            CP_ASYNC16(st + o,         kh + g);
            CP_ASYNC16(st + 8192 + o,  kl + g);
            CP_ASYNC16(st + 16384 + o, v + g);
        }
    };
    load_kv(0, 0);
    CP_ASYNC_COMMIT();

    const int nkt = 2 * qt + 2;
    const int ktmax_w = (qt * 128 + wid * 16 + 15) >> 6;
    const int lr = lane & 15, lc = lane >> 4;
    const int r0l = lane >> 2;
    const int c2 = (lane & 3) * 2;
    const int rowg0 = qt * 128 + wid * 16 + r0l;

    float m_i[2] = {-1e30f, -1e30f}, l_i[2] = {0.f, 0.f};
    float oacc[8][4];
    #pragma unroll
    for (int i = 0; i < 8; i++)
        #pragma unroll
        for (int j = 0; j < 4; j++) oacc[i][j] = 0.f;

    for (int kt = 0; kt < nkt; kt++) {
        if (kt + 1 < nkt) load_kv(kt + 1, (kt + 1) & 1);
        CP_ASYNC_COMMIT();
        CP_ASYNC_WAIT1();
        __syncthreads();

        if (kt <= ktmax_w) {
            uint32_t st = sb + 16384 + (kt & 1) * AT_STAGE;
            uint32_t sKh = st, sKl = st + 8192, sV = st + 16384;

            float sacc[8][4];
            #pragma unroll
            for (int i = 0; i < 8; i++)
                #pragma unroll
                for (int j = 0; j < 4; j++) sacc[i][j] = 0.f;

            #pragma unroll
            for (int kg = 0; kg < 4; kg++) {
                uint32_t a0[4];
                ldmx4(a0, sQ + swz(wid * 16 + lr, kg * 32 + lc * 16));
                #pragma unroll
                for (int np = 0; np < 4; np++) {
                    uint32_t bh4[4], bl4[4];
                    uint32_t boff = swz(np * 16 + lr, kg * 32 + lc * 16);
                    ldmx4(bh4, sKh + boff);
                    ldmx4(bl4, sKl + boff);
                    #pragma unroll
                    for (int u = 0; u < 2; u++) {
                        int nt = np * 2 + u;
                        mma_f16(sacc[nt], a0, bh4[u], bh4[u + 2]);
                        mma_f16(sacc[nt], a0, bl4[u], bl4[u + 2]);
                    }
                }
            }

            float rm[2] = {-1e30f, -1e30f};
            #pragma unroll
            for (int nt = 0; nt < 8; nt++) {
                #pragma unroll
                for (int j = 0; j < 4; j++) {
                    int jr = j >> 1;
                    int rowg = rowg0 + jr * 8;
                    int colg = kt * 64 + nt * 8 + c2 + (j & 1);
                    float s = sacc[nt][j] * 0.125f;
                    if (colg > rowg) s = -1e30f;
                    sacc[nt][j] = s;
                    rm[jr] = fmaxf(rm[jr], s);
                }
            }
            #pragma unroll
            for (int jr = 0; jr < 2; jr++) {
                rm[jr] = fmaxf(rm[jr], __shfl_xor_sync(0xffffffffu, rm[jr], 1));
                rm[jr] = fmaxf(rm[jr], __shfl_xor_sync(0xffffffffu, rm[jr], 2));
            }
            float sc[2], rs[2] = {0.f, 0.f};
            #pragma unroll
            for (int jr = 0; jr < 2; jr++) {
                float mn = fmaxf(m_i[jr], rm[jr]);
                sc[jr] = __expf(m_i[jr] - mn);
                m_i[jr] = mn;
            }
            #pragma unroll
            for (int nt = 0; nt < 8; nt++) {
                #pragma unroll
                for (int j = 0; j < 4; j++) {
                    float p = __expf(sacc[nt][j] - m_i[j >> 1]);
                    sacc[nt][j] = p;
                    rs[j >> 1] += p;
                }
            }
            #pragma unroll
            for (int jr = 0; jr < 2; jr++) {
                rs[jr] += __shfl_xor_sync(0xffffffffu, rs[jr], 1);
                rs[jr] += __shfl_xor_sync(0xffffffffu, rs[jr], 2);
                l_i[jr] = l_i[jr] * sc[jr] + rs[jr];
            }
            #pragma unroll
            for (int nt = 0; nt < 8; nt++) {
                #pragma unroll
                for (int j = 0; j < 4; j++) oacc[nt][j] *= sc[j >> 1];
            }

            #pragma unroll
            for (int kc = 0; kc < 4; kc++) {
                uint32_t ph[4], pl[4];
                split2h(sacc[2 * kc][0],     sacc[2 * kc][1],     ph[0], pl[0]);
                split2h(sacc[2 * kc][2],     sacc[2 * kc][3],     ph[1], pl[1]);
                split2h(sacc[2 * kc + 1][0], sacc[2 * kc + 1][1], ph[2], pl[2]);
                split2h(sacc[2 * kc + 1][2], sacc[2 * kc + 1][3], ph[3], pl[3]);
                uint32_t vrow = kc * 16 + ((lane >> 3) & 1) * 8 + (lane & 7);
                #pragma unroll
                for (int dp = 0; dp < 4; dp++) {
                    uint32_t v4[4];
                    ldmx4t(v4, sV + swz(vrow, dp * 32 + (lane >> 4) * 16));
                    mma_f16(oacc[dp * 2],     ph, v4[0], v4[1]);
                    mma_f16(oacc[dp * 2],     pl, v4[0], v4[1]);
                    mma_f16(oacc[dp * 2 + 1], ph, v4[2], v4[3]);
                    mma_f16(oacc[dp * 2 + 1], pl, v4[2], v4[3]);
                }
            }
        }
        __syncthreads();
    }

    float inv[2] = {1.0f / l_i[0], 1.0f / l_i[1]};
    #pragma unroll
    for (int nt = 0; nt < 8; nt++) {
        #pragma unroll
        for (int jr = 0; jr < 2; jr++) {
            float v0 = oacc[nt][jr * 2 + 0] * inv[jr];
            float v1 = oacc[nt][jr * 2 + 1] * inv[jr];
            uint32_t hw, lw;
            split2(v0, v1, hw, lw);
            size_t off = (rowbase + rowg0 + jr * 8) * DD + colq + nt * 8 + c2;
            *reinterpret_cast<uint32_t*>(Oh + off) = hw;
            *reinterpret_cast<uint32_t*>(Ol + off) = lw;
        }
    }
}

// ---------------- launch ----------------
extern "C" void kernel_launch(void* const* d_in, const int* in_sizes, int n_in,
                              void* d_out, int out_size) {
    const float* x     = (const float*)d_in[0];
    const float* ln1_g = (const float*)d_in[1];
    const float* ln1_b = (const float*)d_in[2];
    const float* Wq    = (const float*)d_in[3];
    const float* Wk    = (const float*)d_in[4];
    const float* Wv    = (const float*)d_in[5];
    const float* Wo    = (const float*)d_in[6];
    const float* bo    = (const float*)d_in[7];
    const float* ln2_g = (const float*)d_in[8];
    const float* ln2_b = (const float*)d_in[9];
    const float* W1    = (const float*)d_in[10];
    const float* b1    = (const float*)d_in[11];
    const float* W2    = (const float*)d_in[12];
    const float* b2    = (const float*)d_in[13];
    float* out = (float*)d_out;

    float* x2;
    cudaGetSymbolAddress((void**)&x2, g_x2);
    __nv_bfloat16 *hh, *hl, *ctxh, *ctxl;
    cudaGetSymbolAddress((void**)&hh, g_hh);     cudaGetSymbolAddress((void**)&hl, g_hl);
    cudaGetSymbolAddress((void**)&ctxh, g_ctxh); cudaGetSymbolAddress((void**)&ctxl, g_ctxl);
    __half *qh, *kh, *kl, *vh, *h2, *mid;
    cudaGetSymbolAddress((void**)&qh, g_qh);
    cudaGetSymbolAddress((void**)&kh, g_kh);     cudaGetSymbolAddress((void**)&kl, g_kl);
    cudaGetSymbolAddress((void**)&vh, g_vh);
    cudaGetSymbolAddress((void**)&h2, g_h2);     cudaGetSymbolAddress((void**)&mid, g_mid);

    __nv_bfloat16 *wqh, *wql, *wkh, *wkl, *wvh, *wvl, *woh, *wol;
    cudaGetSymbolAddress((void**)&wqh, g_wqh); cudaGetSymbolAddress((void**)&wql, g_wql);
    cudaGetSymbolAddress((void**)&wkh, g_wkh); cudaGetSymbolAddress((void**)&wkl, g_wkl);
    cudaGetSymbolAddress((void**)&wvh, g_wvh); cudaGetSymbolAddress((void**)&wvl, g_wvl);
    cudaGetSymbolAddress((void**)&woh, g_woh); cudaGetSymbolAddress((void**)&wol, g_wol);
    __half *w1h, *w1l, *w2h, *w2l;
    cudaGetSymbolAddress((void**)&w1h, g_w1h); cudaGetSymbolAddress((void**)&w1l, g_w1l);
    cudaGetSymbolAddress((void**)&w2h, g_w2h); cudaGetSymbolAddress((void**)&w2l, g_w2l);

    static int attr_set = 0;
    if (!attr_set) {
        cudaFuncSetAttribute(attn_mma_kernel, cudaFuncAttributeMaxDynamicSharedMemorySize, AT_SMEM);
        cudaFuncSetAttribute(gemm3_qkv,  cudaFuncAttributeMaxDynamicSharedMemorySize, GEMM3_SMEM);
        cudaFuncSetAttribute(gemm3_f32,  cudaFuncAttributeMaxDynamicSharedMemorySize, GEMM3_SMEM);
        cudaFuncSetAttribute(gemm2_gelu, cudaFuncAttributeMaxDynamicSharedMemorySize, GEMM2_SMEM);
        cudaFuncSetAttribute(gemm2_f32,  cudaFuncAttributeMaxDynamicSharedMemorySize, GEMM2_SMEM);
        attr_set = 1;
    }

    const int M = MROWS;
    dim3 tb(32, 8);

    wsplit_bf16<<<dim3(DD / 32, DD / 32), tb>>>(Wq, wqh, wql, DD, DD);
    wsplit_bf16<<<dim3(DD / 32, DD / 32), tb>>>(Wk, wkh, wkl, DD, DD);
    wsplit_bf16<<<dim3(DD / 32, DD / 32), tb>>>(Wv, wvh, wvl, DD, DD);
    wsplit_bf16<<<dim3(DD / 32, DD / 32), tb>>>(Wo, woh, wol, DD, DD);
    wsplit_f16 <<<dim3(DFF / 32, DD / 32), tb>>>(W1, w1h, w1l, DD, DFF);
    wsplit_f16 <<<dim3(DD / 32, DFF / 32), tb>>>(W2, w2h, w2l, DFF, DD);

    ln_bf16pair<<<M, 256>>>(x, ln1_g, ln1_b, hh, hl);

    dim3 gQKV(DD / 128, M / 128, 3);
    gemm3_qkv<<<gQKV, 256, GEMM3_SMEM>>>(hh, hl, wqh, wql, wkh, wkl, wvh, wvl,
                                         qh, kh, kl, vh);

    dim3 gA(SS / 128, BB * HH);
    attn_mma_kernel<<<gA, 256, AT_SMEM>>>(qh, kh, kl, vh, ctxh, ctxl);

    dim3 gDD(DD / 128, M / 128);
    gemm3_f32<<<gDD, 256, GEMM3_SMEM>>>(ctxh, ctxl, woh, wol, x2, DD, DD, bo, x);

    ln_f16<<<M, 256>>>(x2, ln2_g, ln2_b, h2);

    dim3 gFF(DFF / 128, M / 128);
    gemm2_gelu<<<gFF, 256, GEMM2_SMEM>>>(h2, w1h, w1l, mid, DFF, DD, b1);

    gemm2_f32<<<gDD, 256, GEMM2_SMEM>>>(mid, w2h, w2l, out, DD, DFF, b2, x2);
}

// round 9
// speedup vs baseline: 1.9117x; 1.1137x over previous
#include <cuda_runtime.h>
#include <cuda_bf16.h>
#include <cuda_fp16.h>
#include <math.h>
#include <cstdint>

#define BB 2
#define SS 2048
#define DD 1024
#define HH 16
#define HDIM 64
#define DFF 4096
#define MROWS (BB * SS)

// ---------------- PTX helpers ----------------
__device__ __forceinline__ uint32_t smem_to_u32(const void* p) {
    uint32_t a;
    asm("{ .reg .u64 t; cvta.to.shared.u64 t, %1; cvt.u32.u64 %0, t; }" : "=r"(a) : "l"(p));
    return a;
}
__device__ __forceinline__ void ldmx4(uint32_t* r, uint32_t a) {
    asm volatile("ldmatrix.sync.aligned.m8n8.x4.shared.b16 {%0,%1,%2,%3}, [%4];"
        : "=r"(r[0]), "=r"(r[1]), "=r"(r[2]), "=r"(r[3]) : "r"(a));
}
__device__ __forceinline__ void ldmx4t(uint32_t* r, uint32_t a) {
    asm volatile("ldmatrix.sync.aligned.m8n8.x4.trans.shared.b16 {%0,%1,%2,%3}, [%4];"
        : "=r"(r[0]), "=r"(r[1]), "=r"(r[2]), "=r"(r[3]) : "r"(a));
}
__device__ __forceinline__ void mma_f16(float* c, const uint32_t* a, uint32_t b0, uint32_t b1) {
    asm volatile("mma.sync.aligned.m16n8k16.row.col.f32.f16.f16.f32 "
        "{%0,%1,%2,%3}, {%4,%5,%6,%7}, {%8,%9}, {%0,%1,%2,%3};"
        : "+f"(c[0]), "+f"(c[1]), "+f"(c[2]), "+f"(c[3])
        : "r"(a[0]), "r"(a[1]), "r"(a[2]), "r"(a[3]), "r"(b0), "r"(b1));
}
#define CP_ASYNC16(s, g) asm volatile("cp.async.cg.shared.global [%0], [%1], 16;" :: "r"(s), "l"(g))
#define CP_ASYNC_COMMIT() asm volatile("cp.async.commit_group;" ::: "memory")
#define CP_ASYNC_WAIT2()  asm volatile("cp.async.wait_group 2;" ::: "memory")
#define CP_ASYNC_WAIT1()  asm volatile("cp.async.wait_group 1;" ::: "memory")

__device__ __forceinline__ uint32_t swz(uint32_t row, uint32_t colbyte) {
    return row * 128 + (colbyte ^ ((row & 7) << 4));
}
__device__ __forceinline__ void split2h(float a, float b, uint32_t& hw, uint32_t& lw) {
    __half2 h = __floats2half2_rn(a, b);
    float2 f = __half22float2(h);
    __half2 l = __floats2half2_rn(a - f.x, b - f.y);
    hw = *reinterpret_cast<const uint32_t*>(&h);
    lw = *reinterpret_cast<const uint32_t*>(&l);
}
__device__ __forceinline__ float gelu_exact(float v) {
    return 0.5f * v * (1.0f + erff(v * 0.70710678118654752f));
}

// ---------------- scratch ----------------
__device__ float g_x2[MROWS * DD];
__device__ __half g_h2 [MROWS * DD];                    // LN output (fp16)
__device__ __half g_q  [MROWS * DD];                    // Q fp16 single
__device__ __half g_kh [MROWS * DD], g_kl[MROWS * DD];  // K fp16 pair
__device__ __half g_v  [MROWS * DD];                    // V fp16 single
__device__ __half g_ctx[MROWS * DD];                    // attention out fp16
__device__ __half g_mid[(size_t)MROWS * DFF];
__device__ __half g_wqh[DD * DD], g_wql[DD * DD];
__device__ __half g_wkh[DD * DD], g_wkl[DD * DD];
__device__ __half g_wvh[DD * DD], g_wvl[DD * DD];
__device__ __half g_woh[DD * DD], g_wol[DD * DD];
__device__ __half g_w1h[(size_t)DD * DFF], g_w1l[(size_t)DD * DFF];
__device__ __half g_w2h[(size_t)DFF * DD], g_w2l[(size_t)DFF * DD];

// ---------------- weight split kernel ----------------
__global__ void wsplit_f16(const float* __restrict__ W, __half* __restrict__ Th,
                           __half* __restrict__ Tl, int K, int N) {
    __shared__ float tile[32][33];
    int bx = blockIdx.x, by = blockIdx.y, tx = threadIdx.x, ty = threadIdx.y;
    #pragma unroll
    for (int i = 0; i < 4; i++)
        tile[ty + 8 * i][tx] = W[(size_t)(by * 32 + ty + 8 * i) * N + bx * 32 + tx];
    __syncthreads();
    #pragma unroll
    for (int i = 0; i < 4; i++) {
        float v = tile[tx][ty + 8 * i];
        __half h = __float2half_rn(v);
        __half l = __float2half_rn(v - __half2float(h));
        size_t o = (size_t)(bx * 32 + ty + 8 * i) * K + by * 32 + tx;
        Th[o] = h; Tl[o] = l;
    }
}

// ---------------- LayerNorm (fp16 out) ----------------
__global__ void ln_f16(const float* __restrict__ x, const float* __restrict__ gamma,
                       const float* __restrict__ beta, __half* __restrict__ y) {
    int row = blockIdx.x, tid = threadIdx.x;
    const float4 v = reinterpret_cast<const float4*>(x + (size_t)row * DD)[tid];
    float s = v.x + v.y + v.z + v.w;
    float sq = v.x * v.x + v.y * v.y + v.z * v.z + v.w * v.w;
    for (int o = 16; o > 0; o >>= 1) {
        s += __shfl_down_sync(0xffffffffu, s, o);
        sq += __shfl_down_sync(0xffffffffu, sq, o);
    }
    __shared__ float ws[8], wq[8];
    int lane = tid & 31, warp = tid >> 5;
    if (lane == 0) { ws[warp] = s; wq[warp] = sq; }
    __syncthreads();
    __shared__ float mu_s, rstd_s;
    if (tid == 0) {
        float ts = 0.f, tq = 0.f;
        #pragma unroll
        for (int i = 0; i < 8; i++) { ts += ws[i]; tq += wq[i]; }
        float mu = ts * (1.0f / DD);
        float var = tq * (1.0f / DD) - mu * mu;
        mu_s = mu; rstd_s = rsqrtf(var + 1e-5f);
    }
    __syncthreads();
    float mu = mu_s, r = rstd_s;
    float4 g4 = reinterpret_cast<const float4*>(gamma)[tid];
    float4 b4 = reinterpret_cast<const float4*>(beta)[tid];
    float o0 = (v.x - mu) * r * g4.x + b4.x;
    float o1 = (v.y - mu) * r * g4.y + b4.y;
    float o2 = (v.z - mu) * r * g4.z + b4.z;
    float o3 = (v.w - mu) * r * g4.w + b4.w;
    __half2 h0 = __floats2half2_rn(o0, o1);
    __half2 h1 = __floats2half2_rn(o2, o3);
    uint2 w = make_uint2(*reinterpret_cast<const uint32_t*>(&h0),
                         *reinterpret_cast<const uint32_t*>(&h1));
    *reinterpret_cast<uint2*>(y + (size_t)row * DD + tid * 4) = w;
}

// ---------------- GEMM core (fp16 2-term) ----------------
// D = A(fp16) @ (Bh+Bl)[N,K]^T.
// mode 1: fp32 + bias + res; 2: fp16 + bias + gelu; 3: fp16 out (pair if Cl)
__device__ __forceinline__ void cpa_tile(uint32_t sdst, const __half* __restrict__ g,
                                         int K, int r0, int k0, int tid) {
    #pragma unroll
    for (int l = 0; l < 4; l++) {
        int f = tid + 256 * l;
        int row = f >> 3, c = f & 7;
        CP_ASYNC16(sdst + swz(row, c * 16), g + (size_t)(r0 + row) * K + k0 + c * 8);
    }
}

#define STAGE2 (3 * 16384)
#define GEMM2_SMEM (3 * STAGE2)

__device__ __forceinline__ void gemm_core(const __half* __restrict__ A,
                                          const __half* __restrict__ B0,
                                          const __half* __restrict__ B1,
                                          float* __restrict__ C,
                                          __half* __restrict__ Ch,
                                          __half* __restrict__ Cl,
                                          int N, int K,
                                          const float* __restrict__ bias,
                                          const float* __restrict__ res, int mode) {
    extern __shared__ char smem[];
    const uint32_t sb0 = smem_to_u32(smem);
    const int tid = threadIdx.x;
    const int wid = tid >> 5, lane = tid & 31;
    const int wm = wid >> 2, wn = wid & 3;
    const int m0 = blockIdx.y * 128, n0 = blockIdx.x * 128;
    const int lr = lane & 15, lc = lane >> 4;

    float acc[4][4][4];
    #pragma unroll
    for (int i = 0; i < 4; i++)
        #pragma unroll
        for (int j = 0; j < 4; j++)
            #pragma unroll
            for (int p = 0; p < 4; p++) acc[i][j][p] = 0.f;

    const int T = K >> 6;
    auto load_tile = [&](int t, int s) {
        uint32_t sb = sb0 + s * STAGE2;
        int k0 = t * 64;
        cpa_tile(sb,         A,  K, m0, k0, tid);
        cpa_tile(sb + 16384, B0, K, n0, k0, tid);
        cpa_tile(sb + 32768, B1, K, n0, k0, tid);
    };

    load_tile(0, 0);
    CP_ASYNC_COMMIT();
    if (T > 1) load_tile(1, 1);
    CP_ASYNC_COMMIT();

    for (int t = 0; t < T; t++) {
        if (t + 2 < T) load_tile(t + 2, (t + 2) % 3);
        CP_ASYNC_COMMIT();
        CP_ASYNC_WAIT2();
        __syncthreads();

        const uint32_t sb = sb0 + (t % 3) * STAGE2;
        const uint32_t sA = sb, sB0 = sb + 16384, sB1 = sb + 32768;
        #pragma unroll
        for (int kg = 0; kg < 4; kg++) {
            uint32_t a0[4][4];
            #pragma unroll
            for (int mt = 0; mt < 4; mt++)
                ldmx4(a0[mt], sA + swz(wm * 64 + mt * 16 + lr, kg * 32 + lc * 16));
            uint32_t bh4[2][4], bl4[2][4];
            #pragma unroll
            for (int np = 0; np < 2; np++) {
                uint32_t off = swz(wn * 32 + np * 16 + lr, kg * 32 + lc * 16);
                ldmx4(bh4[np], sB0 + off);
                ldmx4(bl4[np], sB1 + off);
            }
            #pragma unroll
            for (int mt = 0; mt < 4; mt++) {
                #pragma unroll
                for (int nt = 0; nt < 4; nt++) {
                    int np = nt >> 1, u = nt & 1;
                    mma_f16(acc[mt][nt], a0[mt], bh4[np][u], bh4[np][u + 2]);
                    mma_f16(acc[mt][nt], a0[mt], bl4[np][u], bl4[np][u + 2]);
                }
            }
        }
        __syncthreads();
    }

    #pragma unroll
    for (int mt = 0; mt < 4; mt++) {
        #pragma unroll
        for (int nt = 0; nt < 4; nt++) {
            int r0 = m0 + wm * 64 + mt * 16 + (lane >> 2);
            int c0 = n0 + wn * 32 + nt * 8 + (lane & 3) * 2;
            float bv0 = 0.f, bv1 = 0.f;
            if (mode == 1 || mode == 2) { bv0 = bias[c0]; bv1 = bias[c0 + 1]; }
            #pragma unroll
            for (int half = 0; half < 2; half++) {
                int r = r0 + half * 8;
                float v0 = acc[mt][nt][half * 2 + 0] + bv0;
                float v1 = acc[mt][nt][half * 2 + 1] + bv1;
                if (mode == 3) {
                    uint32_t hw, lw;
                    split2h(v0, v1, hw, lw);
                    *reinterpret_cast<uint32_t*>(Ch + (size_t)r * N + c0) = hw;
                    if (Cl) *reinterpret_cast<uint32_t*>(Cl + (size_t)r * N + c0) = lw;
                } else if (mode == 2) {
                    v0 = gelu_exact(v0); v1 = gelu_exact(v1);
                    __half2 hv = __floats2half2_rn(v0, v1);
                    *reinterpret_cast<uint32_t*>(Ch + (size_t)r * N + c0) =
                        *reinterpret_cast<const uint32_t*>(&hv);
                } else {
                    float2 rr = *(const float2*)(res + (size_t)r * N + c0);
                    *(float2*)(C + (size_t)r * N + c0) = make_float2(v0 + rr.x, v1 + rr.y);
                }
            }
        }
    }
}

__global__ void __launch_bounds__(256, 1)
gemm2_qkv(const __half* __restrict__ A,
          const __half* __restrict__ wqh, const __half* __restrict__ wql,
          const __half* __restrict__ wkh, const __half* __restrict__ wkl,
          const __half* __restrict__ wvh, const __half* __restrict__ wvl,
          __half* __restrict__ q, __half* __restrict__ kh, __half* __restrict__ kl,
          __half* __restrict__ v) {
    const __half* B0 = (blockIdx.z == 0) ? wqh : (blockIdx.z == 1) ? wkh : wvh;
    const __half* B1 = (blockIdx.z == 0) ? wql : (blockIdx.z == 1) ? wkl : wvl;
    __half* Ch = (blockIdx.z == 0) ? q : (blockIdx.z == 1) ? kh : v;
    __half* Cl = (blockIdx.z == 1) ? kl : nullptr;
    gemm_core(A, B0, B1, nullptr, Ch, Cl, DD, DD, nullptr, nullptr, 3);
}
__global__ void __launch_bounds__(256, 1)
gemm2_f32(const __half* __restrict__ A,
          const __half* __restrict__ B0, const __half* __restrict__ B1,
          float* __restrict__ C, int N, int K,
          const float* __restrict__ bias, const float* __restrict__ res) {
    gemm_core(A, B0, B1, C, nullptr, nullptr, N, K, bias, res, 1);
}
__global__ void __launch_bounds__(256, 1)
gemm2_gelu(const __half* __restrict__ A,
           const __half* __restrict__ B0, const __half* __restrict__ B1,
           __half* __restrict__ Cf, int N, int K, const float* __restrict__ bias) {
    gemm_core(A, B0, B1, nullptr, Cf, nullptr, N, K, bias, nullptr, 2);
}

// ---------------- Flash attention fp16 2-term ----------------
// S = Q @ (Kh+Kl)^T ; O = (Ph+Pl) @ V.  Output ctx fp16 single.
#define AT_STAGE 24576
#define AT_SMEM (16384 + 2 * AT_STAGE)

__global__ void __launch_bounds__(256, 2)
attn_mma_kernel(const __half* __restrict__ q, const __half* __restrict__ kh,
                const __half* __restrict__ kl, const __half* __restrict__ v,
                __half* __restrict__ O) {
    extern __shared__ char smem[];
    const uint32_t sb = smem_to_u32(smem);
    const uint32_t sQ = sb;
    const int tid = threadIdx.x, wid = tid >> 5, lane = tid & 31;
    const int qt = blockIdx.x;
    const int h = blockIdx.y & 15, b = blockIdx.y >> 4;
    const size_t rowbase = (size_t)b * SS;
    const int colq = h * HDIM;

    #pragma unroll
    for (int l = 0; l < 4; l++) {
        int f = tid + 256 * l;
        int row = f >> 3, c = f & 7;
        CP_ASYNC16(sQ + swz(row, c * 16),
                   q + (rowbase + qt * 128 + row) * DD + colq + c * 8);
    }
    CP_ASYNC_COMMIT();

    auto load_kv = [&](int kt, int s) {
        uint32_t st = sb + 16384 + s * AT_STAGE;
        #pragma unroll
        for (int l = 0; l < 2; l++) {
            int f = tid + 256 * l;
            int row = f >> 3, c = f & 7;
            size_t g = (rowbase + kt * 64 + row) * DD + colq + c * 8;
            uint32_t o = swz(row, c * 16);
            CP_ASYNC16(st + o,         kh + g);
            CP_ASYNC16(st + 8192 + o,  kl + g);
            CP_ASYNC16(st + 16384 + o, v + g);
        }
    };
    load_kv(0, 0);
    CP_ASYNC_COMMIT();

    const int nkt = 2 * qt + 2;
    const int ktmax_w = (qt * 128 + wid * 16 + 15) >> 6;
    const int lr = lane & 15, lc = lane >> 4;
    const int r0l = lane >> 2;
    const int c2 = (lane & 3) * 2;
    const int rowg0 = qt * 128 + wid * 16 + r0l;

    float m_i[2] = {-1e30f, -1e30f}, l_i[2] = {0.f, 0.f};
    float oacc[8][4];
    #pragma unroll
    for (int i = 0; i < 8; i++)
        #pragma unroll
        for (int j = 0; j < 4; j++) oacc[i][j] = 0.f;

    for (int kt = 0; kt < nkt; kt++) {
        if (kt + 1 < nkt) load_kv(kt + 1, (kt + 1) & 1);
        CP_ASYNC_COMMIT();
        CP_ASYNC_WAIT1();
        __syncthreads();

        if (kt <= ktmax_w) {
            uint32_t st = sb + 16384 + (kt & 1) * AT_STAGE;
            uint32_t sKh = st, sKl = st + 8192, sV = st + 16384;

            float sacc[8][4];
            #pragma unroll
            for (int i = 0; i < 8; i++)
                #pragma unroll
                for (int j = 0; j < 4; j++) sacc[i][j] = 0.f;

            #pragma unroll
            for (int kg = 0; kg < 4; kg++) {
                uint32_t a0[4];
                ldmx4(a0, sQ + swz(wid * 16 + lr, kg * 32 + lc * 16));
                #pragma unroll
                for (int np = 0; np < 4; np++) {
                    uint32_t bh4[4], bl4[4];
                    uint32_t boff = swz(np * 16 + lr, kg * 32 + lc * 16);
                    ldmx4(bh4, sKh + boff);
                    ldmx4(bl4, sKl + boff);
                    #pragma unroll
                    for (int u = 0; u < 2; u++) {
                        int nt = np * 2 + u;
                        mma_f16(sacc[nt], a0, bh4[u], bh4[u + 2]);
                        mma_f16(sacc[nt], a0, bl4[u], bl4[u + 2]);
                    }
                }
            }

            float rm[2] = {-1e30f, -1e30f};
            #pragma unroll
            for (int nt = 0; nt < 8; nt++) {
                #pragma unroll
                for (int j = 0; j < 4; j++) {
                    int jr = j >> 1;
                    int rowg = rowg0 + jr * 8;
                    int colg = kt * 64 + nt * 8 + c2 + (j & 1);
                    float s = sacc[nt][j] * 0.125f;
                    if (colg > rowg) s = -1e30f;
                    sacc[nt][j] = s;
                    rm[jr] = fmaxf(rm[jr], s);
                }
            }
            #pragma unroll
            for (int jr = 0; jr < 2; jr++) {
                rm[jr] = fmaxf(rm[jr], __shfl_xor_sync(0xffffffffu, rm[jr], 1));
                rm[jr] = fmaxf(rm[jr], __shfl_xor_sync(0xffffffffu, rm[jr], 2));
            }
            float sc[2], rs[2] = {0.f, 0.f};
            #pragma unroll
            for (int jr = 0; jr < 2; jr++) {
                float mn = fmaxf(m_i[jr], rm[jr]);
                sc[jr] = __expf(m_i[jr] - mn);
                m_i[jr] = mn;
            }
            #pragma unroll
            for (int nt = 0; nt < 8; nt++) {
                #pragma unroll
                for (int j = 0; j < 4; j++) {
                    float p = __expf(sacc[nt][j] - m_i[j >> 1]);
                    sacc[nt][j] = p;
                    rs[j >> 1] += p;
                }
            }
            #pragma unroll
            for (int jr = 0; jr < 2; jr++) {
                rs[jr] += __shfl_xor_sync(0xffffffffu, rs[jr], 1);
                rs[jr] += __shfl_xor_sync(0xffffffffu, rs[jr], 2);
                l_i[jr] = l_i[jr] * sc[jr] + rs[jr];
            }
            #pragma unroll
            for (int nt = 0; nt < 8; nt++) {
                #pragma unroll
                for (int j = 0; j < 4; j++) oacc[nt][j] *= sc[j >> 1];
            }

            #pragma unroll
            for (int kc = 0; kc < 4; kc++) {
                uint32_t ph[4], pl[4];
                split2h(sacc[2 * kc][0],     sacc[2 * kc][1],     ph[0], pl[0]);
                split2h(sacc[2 * kc][2],     sacc[2 * kc][3],     ph[1], pl[1]);
                split2h(sacc[2 * kc + 1][0], sacc[2 * kc + 1][1], ph[2], pl[2]);
                split2h(sacc[2 * kc + 1][2], sacc[2 * kc + 1][3], ph[3], pl[3]);
                uint32_t vrow = kc * 16 + ((lane >> 3) & 1) * 8 + (lane & 7);
                #pragma unroll
                for (int dp = 0; dp < 4; dp++) {
                    uint32_t v4[4];
                    ldmx4t(v4, sV + swz(vrow, dp * 32 + (lane >> 4) * 16));
                    mma_f16(oacc[dp * 2],     ph, v4[0], v4[1]);
                    mma_f16(oacc[dp * 2],     pl, v4[0], v4[1]);
                    mma_f16(oacc[dp * 2 + 1], ph, v4[2], v4[3]);
                    mma_f16(oacc[dp * 2 + 1], pl, v4[2], v4[3]);
                }
            }
        }
        __syncthreads();
    }

    float inv[2] = {1.0f / l_i[0], 1.0f / l_i[1]};
    #pragma unroll
    for (int nt = 0; nt < 8; nt++) {
        #pragma unroll
        for (int jr = 0; jr < 2; jr++) {
            float v0 = oacc[nt][jr * 2 + 0] * inv[jr];
            float v1 = oacc[nt][jr * 2 + 1] * inv[jr];
            __half2 hv = __floats2half2_rn(v0, v1);
            size_t off = (rowbase + rowg0 + jr * 8) * DD + colq + nt * 8 + c2;
            *reinterpret_cast<uint32_t*>(O + off) = *reinterpret_cast<const uint32_t*>(&hv);
        }
    }
}

// ---------------- launch ----------------
extern "C" void kernel_launch(void* const* d_in, const int* in_sizes, int n_in,
                              void* d_out, int out_size) {
    const float* x     = (const float*)d_in[0];
    const float* ln1_g = (const float*)d_in[1];
    const float* ln1_b = (const float*)d_in[2];
    const float* Wq    = (const float*)d_in[3];
    const float* Wk    = (const float*)d_in[4];
    const float* Wv    = (const float*)d_in[5];
    const float* Wo    = (const float*)d_in[6];
    const float* bo    = (const float*)d_in[7];
    const float* ln2_g = (const float*)d_in[8];
    const float* ln2_b = (const float*)d_in[9];
    const float* W1    = (const float*)d_in[10];
    const float* b1    = (const float*)d_in[11];
    const float* W2    = (const float*)d_in[12];
    const float* b2    = (const float*)d_in[13];
    float* out = (float*)d_out;

    float* x2;
    cudaGetSymbolAddress((void**)&x2, g_x2);
    __half *h2, *q, *kh, *kl, *v, *ctx, *mid;
    cudaGetSymbolAddress((void**)&h2, g_h2);
    cudaGetSymbolAddress((void**)&q, g_q);
    cudaGetSymbolAddress((void**)&kh, g_kh);  cudaGetSymbolAddress((void**)&kl, g_kl);
    cudaGetSymbolAddress((void**)&v, g_v);
    cudaGetSymbolAddress((void**)&ctx, g_ctx);
    cudaGetSymbolAddress((void**)&mid, g_mid);

    __half *wqh, *wql, *wkh, *wkl, *wvh, *wvl, *woh, *wol, *w1h, *w1l, *w2h, *w2l;
    cudaGetSymbolAddress((void**)&wqh, g_wqh); cudaGetSymbolAddress((void**)&wql, g_wql);
    cudaGetSymbolAddress((void**)&wkh, g_wkh); cudaGetSymbolAddress((void**)&wkl, g_wkl);
    cudaGetSymbolAddress((void**)&wvh, g_wvh); cudaGetSymbolAddress((void**)&wvl, g_wvl);
    cudaGetSymbolAddress((void**)&woh, g_woh); cudaGetSymbolAddress((void**)&wol, g_wol);
    cudaGetSymbolAddress((void**)&w1h, g_w1h); cudaGetSymbolAddress((void**)&w1l, g_w1l);
    cudaGetSymbolAddress((void**)&w2h, g_w2h); cudaGetSymbolAddress((void**)&w2l, g_w2l);

    static int attr_set = 0;
    if (!attr_set) {
        cudaFuncSetAttribute(attn_mma_kernel, cudaFuncAttributeMaxDynamicSharedMemorySize, AT_SMEM);
        cudaFuncSetAttribute(gemm2_qkv,  cudaFuncAttributeMaxDynamicSharedMemorySize, GEMM2_SMEM);
        cudaFuncSetAttribute(gemm2_f32,  cudaFuncAttributeMaxDynamicSharedMemorySize, GEMM2_SMEM);
        cudaFuncSetAttribute(gemm2_gelu, cudaFuncAttributeMaxDynamicSharedMemorySize, GEMM2_SMEM);
        attr_set = 1;
    }

    const int M = MROWS;
    dim3 tb(32, 8);

    wsplit_f16<<<dim3(DD / 32, DD / 32), tb>>>(Wq, wqh, wql, DD, DD);
    wsplit_f16<<<dim3(DD / 32, DD / 32), tb>>>(Wk, wkh, wkl, DD, DD);
    wsplit_f16<<<dim3(DD / 32, DD / 32), tb>>>(Wv, wvh, wvl, DD, DD);
    wsplit_f16<<<dim3(DD / 32, DD / 32), tb>>>(Wo, woh, wol, DD, DD);
    wsplit_f16<<<dim3(DFF / 32, DD / 32), tb>>>(W1, w1h, w1l, DD, DFF);
    wsplit_f16<<<dim3(DD / 32, DFF / 32), tb>>>(W2, w2h, w2l, DFF, DD);

    ln_f16<<<M, 256>>>(x, ln1_g, ln1_b, h2);

    dim3 gQKV(DD / 128, M / 128, 3);
    gemm2_qkv<<<gQKV, 256, GEMM2_SMEM>>>(h2, wqh, wql, wkh, wkl, wvh, wvl, q, kh, kl, v);

    dim3 gA(SS / 128, BB * HH);
    attn_mma_kernel<<<gA, 256, AT_SMEM>>>(q, kh, kl, v, ctx);

    dim3 gDD(DD / 128, M / 128);
    gemm2_f32<<<gDD, 256, GEMM2_SMEM>>>(ctx, woh, wol, x2, DD, DD, bo, x);

    ln_f16<<<M, 256>>>(x2, ln2_g, ln2_b, h2);

    dim3 gFF(DFF / 128, M / 128);
    gemm2_gelu<<<gFF, 256, GEMM2_SMEM>>>(h2, w1h, w1l, mid, DFF, DD, b1);

    gemm2_f32<<<gDD, 256, GEMM2_SMEM>>>(mid, w2h, w2l, out, DD, DFF, b2, x2);
}

// round 10
// speedup vs baseline: 3.2567x; 1.7035x over previous
#include <cuda_runtime.h>
#include <cuda_fp16.h>
#include <math.h>
#include <cstdint>

#define BB 2
#define SS 2048
#define DD 1024
#define HH 16
#define HDIM 64
#define DFF 4096
#define MROWS (BB * SS)

// ---------------- PTX helpers ----------------
__device__ __forceinline__ uint32_t smem_to_u32(const void* p) {
    uint32_t a;
    asm("{ .reg .u64 t; cvta.to.shared.u64 t, %1; cvt.u32.u64 %0, t; }" : "=r"(a) : "l"(p));
    return a;
}
__device__ __forceinline__ void ldmx4(uint32_t* r, uint32_t a) {
    asm volatile("ldmatrix.sync.aligned.m8n8.x4.shared.b16 {%0,%1,%2,%3}, [%4];"
        : "=r"(r[0]), "=r"(r[1]), "=r"(r[2]), "=r"(r[3]) : "r"(a));
}
__device__ __forceinline__ void ldmx4t(uint32_t* r, uint32_t a) {
    asm volatile("ldmatrix.sync.aligned.m8n8.x4.trans.shared.b16 {%0,%1,%2,%3}, [%4];"
        : "=r"(r[0]), "=r"(r[1]), "=r"(r[2]), "=r"(r[3]) : "r"(a));
}
__device__ __forceinline__ void mma_f16(float* c, const uint32_t* a, uint32_t b0, uint32_t b1) {
    asm volatile("mma.sync.aligned.m16n8k16.row.col.f32.f16.f16.f32 "
        "{%0,%1,%2,%3}, {%4,%5,%6,%7}, {%8,%9}, {%0,%1,%2,%3};"
        : "+f"(c[0]), "+f"(c[1]), "+f"(c[2]), "+f"(c[3])
        : "r"(a[0]), "r"(a[1]), "r"(a[2]), "r"(a[3]), "r"(b0), "r"(b1));
}
#define CP_ASYNC16(s, g) asm volatile("cp.async.cg.shared.global [%0], [%1], 16;" :: "r"(s), "l"(g))
#define CP_ASYNC_COMMIT() asm volatile("cp.async.commit_group;" ::: "memory")
#define CP_ASYNC_WAIT2()  asm volatile("cp.async.wait_group 2;" ::: "memory")
#define CP_ASYNC_WAIT1()  asm volatile("cp.async.wait_group 1;" ::: "memory")

__device__ __forceinline__ uint32_t swz(uint32_t row, uint32_t colbyte) {
    return row * 128 + (colbyte ^ ((row & 7) << 4));
}
__device__ __forceinline__ float gelu_exact(float v) {
    return 0.5f * v * (1.0f + erff(v * 0.70710678118654752f));
}

// ---------------- scratch ----------------
__device__ float g_x2[MROWS * DD];
__device__ __half g_h2 [MROWS * DD];
__device__ __half g_q  [MROWS * DD];
__device__ __half g_k  [MROWS * DD];
__device__ __half g_v  [MROWS * DD];
__device__ __half g_ctx[MROWS * DD];
__device__ __half g_mid[(size_t)MROWS * DFF];
__device__ __half g_wq[DD * DD], g_wk[DD * DD], g_wv[DD * DD], g_wo[DD * DD];
__device__ __half g_w1[(size_t)DD * DFF], g_w2[(size_t)DFF * DD];

// ---------------- weight transpose (fp16 single) ----------------
__global__ void wsplit_f16(const float* __restrict__ W, __half* __restrict__ T,
                           int K, int N) {
    __shared__ float tile[32][33];
    int bx = blockIdx.x, by = blockIdx.y, tx = threadIdx.x, ty = threadIdx.y;
    #pragma unroll
    for (int i = 0; i < 4; i++)
        tile[ty + 8 * i][tx] = W[(size_t)(by * 32 + ty + 8 * i) * N + bx * 32 + tx];
    __syncthreads();
    #pragma unroll
    for (int i = 0; i < 4; i++) {
        float v = tile[tx][ty + 8 * i];
        T[(size_t)(bx * 32 + ty + 8 * i) * K + by * 32 + tx] = __float2half_rn(v);
    }
}

// ---------------- LayerNorm (fp16 out) ----------------
__global__ void ln_f16(const float* __restrict__ x, const float* __restrict__ gamma,
                       const float* __restrict__ beta, __half* __restrict__ y) {
    int row = blockIdx.x, tid = threadIdx.x;
    const float4 v = reinterpret_cast<const float4*>(x + (size_t)row * DD)[tid];
    float s = v.x + v.y + v.z + v.w;
    float sq = v.x * v.x + v.y * v.y + v.z * v.z + v.w * v.w;
    for (int o = 16; o > 0; o >>= 1) {
        s += __shfl_down_sync(0xffffffffu, s, o);
        sq += __shfl_down_sync(0xffffffffu, sq, o);
    }
    __shared__ float ws[8], wq[8];
    int lane = tid & 31, warp = tid >> 5;
    if (lane == 0) { ws[warp] = s; wq[warp] = sq; }
    __syncthreads();
    __shared__ float mu_s, rstd_s;
    if (tid == 0) {
        float ts = 0.f, tq = 0.f;
        #pragma unroll
        for (int i = 0; i < 8; i++) { ts += ws[i]; tq += wq[i]; }
        float mu = ts * (1.0f / DD);
        float var = tq * (1.0f / DD) - mu * mu;
        mu_s = mu; rstd_s = rsqrtf(var + 1e-5f);
    }
    __syncthreads();
    float mu = mu_s, r = rstd_s;
    float4 g4 = reinterpret_cast<const float4*>(gamma)[tid];
    float4 b4 = reinterpret_cast<const float4*>(beta)[tid];
    float o0 = (v.x - mu) * r * g4.x + b4.x;
    float o1 = (v.y - mu) * r * g4.y + b4.y;
    float o2 = (v.z - mu) * r * g4.z + b4.z;
    float o3 = (v.w - mu) * r * g4.w + b4.w;
    __half2 h0 = __floats2half2_rn(o0, o1);
    __half2 h1 = __floats2half2_rn(o2, o3);
    uint2 w = make_uint2(*reinterpret_cast<const uint32_t*>(&h0),
                         *reinterpret_cast<const uint32_t*>(&h1));
    *reinterpret_cast<uint2*>(y + (size_t)row * DD + tid * 4) = w;
}

// ---------------- GEMM core (plain fp16) ----------------
// D = A(fp16)[M,K] @ B(fp16)[N,K]^T.
// mode 1: fp32 + bias + res; 2: fp16 + bias + gelu; 3: fp16 plain
__device__ __forceinline__ void cpa_tile(uint32_t sdst, const __half* __restrict__ g,
                                         int K, int r0, int k0, int tid) {
    #pragma unroll
    for (int l = 0; l < 4; l++) {
        int f = tid + 256 * l;
        int row = f >> 3, c = f & 7;
        CP_ASYNC16(sdst + swz(row, c * 16), g + (size_t)(r0 + row) * K + k0 + c * 8);
    }
}

#define STAGE1 (2 * 16384)
#define GEMM_SMEM (3 * STAGE1)

__device__ __forceinline__ void gemm_core(const __half* __restrict__ A,
                                          const __half* __restrict__ B,
                                          float* __restrict__ C,
                                          __half* __restrict__ Ch,
                                          int N, int K,
                                          const float* __restrict__ bias,
                                          const float* __restrict__ res, int mode) {
    extern __shared__ char smem[];
    const uint32_t sb0 = smem_to_u32(smem);
    const int tid = threadIdx.x;
    const int wid = tid >> 5, lane = tid & 31;
    const int wm = wid >> 2, wn = wid & 3;
    const int m0 = blockIdx.y * 128, n0 = blockIdx.x * 128;
    const int lr = lane & 15, lc = lane >> 4;

    float acc[4][4][4];
    #pragma unroll
    for (int i = 0; i < 4; i++)
        #pragma unroll
        for (int j = 0; j < 4; j++)
            #pragma unroll
            for (int p = 0; p < 4; p++) acc[i][j][p] = 0.f;

    const int T = K >> 6;
    auto load_tile = [&](int t, int s) {
        uint32_t sb = sb0 + s * STAGE1;
        int k0 = t * 64;
        cpa_tile(sb,         A, K, m0, k0, tid);
        cpa_tile(sb + 16384, B, K, n0, k0, tid);
    };

    load_tile(0, 0);
    CP_ASYNC_COMMIT();
    if (T > 1) load_tile(1, 1);
    CP_ASYNC_COMMIT();

    for (int t = 0; t < T; t++) {
        if (t + 2 < T) load_tile(t + 2, (t + 2) % 3);
        CP_ASYNC_COMMIT();
        CP_ASYNC_WAIT2();
        __syncthreads();

        const uint32_t sb = sb0 + (t % 3) * STAGE1;
        const uint32_t sA = sb, sB = sb + 16384;
        #pragma unroll
        for (int kg = 0; kg < 4; kg++) {
            uint32_t a0[4][4];
            #pragma unroll
            for (int mt = 0; mt < 4; mt++)
                ldmx4(a0[mt], sA + swz(wm * 64 + mt * 16 + lr, kg * 32 + lc * 16));
            uint32_t b4[2][4];
            #pragma unroll
            for (int np = 0; np < 2; np++)
                ldmx4(b4[np], sB + swz(wn * 32 + np * 16 + lr, kg * 32 + lc * 16));
            #pragma unroll
            for (int mt = 0; mt < 4; mt++) {
                #pragma unroll
                for (int nt = 0; nt < 4; nt++) {
                    int np = nt >> 1, u = nt & 1;
                    mma_f16(acc[mt][nt], a0[mt], b4[np][u], b4[np][u + 2]);
                }
            }
        }
        __syncthreads();
    }

    #pragma unroll
    for (int mt = 0; mt < 4; mt++) {
        #pragma unroll
        for (int nt = 0; nt < 4; nt++) {
            int r0 = m0 + wm * 64 + mt * 16 + (lane >> 2);
            int c0 = n0 + wn * 32 + nt * 8 + (lane & 3) * 2;
            float bv0 = 0.f, bv1 = 0.f;
            if (mode == 1 || mode == 2) { bv0 = bias[c0]; bv1 = bias[c0 + 1]; }
            #pragma unroll
            for (int half = 0; half < 2; half++) {
                int r = r0 + half * 8;
                float v0 = acc[mt][nt][half * 2 + 0] + bv0;
                float v1 = acc[mt][nt][half * 2 + 1] + bv1;
                if (mode == 3) {
                    __half2 hv = __floats2half2_rn(v0, v1);
                    *reinterpret_cast<uint32_t*>(Ch + (size_t)r * N + c0) =
                        *reinterpret_cast<const uint32_t*>(&hv);
                } else if (mode == 2) {
                    v0 = gelu_exact(v0); v1 = gelu_exact(v1);
                    __half2 hv = __floats2half2_rn(v0, v1);
                    *reinterpret_cast<uint32_t*>(Ch + (size_t)r * N + c0) =
                        *reinterpret_cast<const uint32_t*>(&hv);
                } else {
                    float2 rr = *(const float2*)(res + (size_t)r * N + c0);
                    *(float2*)(C + (size_t)r * N + c0) = make_float2(v0 + rr.x, v1 + rr.y);
                }
            }
        }
    }
}

__global__ void __launch_bounds__(256, 1)
gemm_qkv(const __half* __restrict__ A,
         const __half* __restrict__ wq, const __half* __restrict__ wk,
         const __half* __restrict__ wv,
         __half* __restrict__ q, __half* __restrict__ k, __half* __restrict__ v) {
    const __half* B = (blockIdx.z == 0) ? wq : (blockIdx.z == 1) ? wk : wv;
    __half* Ch = (blockIdx.z == 0) ? q : (blockIdx.z == 1) ? k : v;
    gemm_core(A, B, nullptr, Ch, DD, DD, nullptr, nullptr, 3);
}
__global__ void __launch_bounds__(256, 1)
gemm_f32(const __half* __restrict__ A, const __half* __restrict__ B,
         float* __restrict__ C, int N, int K,
         const float* __restrict__ bias, const float* __restrict__ res) {
    gemm_core(A, B, C, nullptr, N, K, bias, res, 1);
}
__global__ void __launch_bounds__(256, 1)
gemm_gelu(const __half* __restrict__ A, const __half* __restrict__ B,
          __half* __restrict__ Cf, int N, int K, const float* __restrict__ bias) {
    gemm_core(A, B, nullptr, Cf, N, K, bias, nullptr, 2);
}

// ---------------- Flash attention plain fp16 ----------------
// S = Q @ K^T ; O = P @ V.
// smem: Q 16K | 2 stages x {K 8K, V 8K} = 48KB
#define AT_STAGE 16384
#define AT_SMEM (16384 + 2 * AT_STAGE)

__global__ void __launch_bounds__(256, 2)
attn_mma_kernel(const __half* __restrict__ q, const __half* __restrict__ k,
                const __half* __restrict__ v, __half* __restrict__ O) {
    extern __shared__ char smem[];
    const uint32_t sb = smem_to_u32(smem);
    const uint32_t sQ = sb;
    const int tid = threadIdx.x, wid = tid >> 5, lane = tid & 31;
    const int qt = blockIdx.x;
    const int h = blockIdx.y & 15, b = blockIdx.y >> 4;
    const size_t rowbase = (size_t)b * SS;
    const int colq = h * HDIM;

    #pragma unroll
    for (int l = 0; l < 4; l++) {
        int f = tid + 256 * l;
        int row = f >> 3, c = f & 7;
        CP_ASYNC16(sQ + swz(row, c * 16),
                   q + (rowbase + qt * 128 + row) * DD + colq + c * 8);
    }
    CP_ASYNC_COMMIT();

    auto load_kv = [&](int kt, int s) {
        uint32_t st = sb + 16384 + s * AT_STAGE;
        #pragma unroll
        for (int l = 0; l < 2; l++) {
            int f = tid + 256 * l;
            int row = f >> 3, c = f & 7;
            size_t g = (rowbase + kt * 64 + row) * DD + colq + c * 8;
            uint32_t o = swz(row, c * 16);
            CP_ASYNC16(st + o,        k + g);
            CP_ASYNC16(st + 8192 + o, v + g);
        }
    };
    load_kv(0, 0);
    CP_ASYNC_COMMIT();

    const int nkt = 2 * qt + 2;
    const int ktmax_w = (qt * 128 + wid * 16 + 15) >> 6;
    const int lr = lane & 15, lc = lane >> 4;
    const int r0l = lane >> 2;
    const int c2 = (lane & 3) * 2;
    const int rowg0 = qt * 128 + wid * 16 + r0l;

    float m_i[2] = {-1e30f, -1e30f}, l_i[2] = {0.f, 0.f};
    float oacc[8][4];
    #pragma unroll
    for (int i = 0; i < 8; i++)
        #pragma unroll
        for (int j = 0; j < 4; j++) oacc[i][j] = 0.f;

    for (int kt = 0; kt < nkt; kt++) {
        if (kt + 1 < nkt) load_kv(kt + 1, (kt + 1) & 1);
        CP_ASYNC_COMMIT();
        CP_ASYNC_WAIT1();
        __syncthreads();

        if (kt <= ktmax_w) {
            uint32_t st = sb + 16384 + (kt & 1) * AT_STAGE;
            uint32_t sK = st, sV = st + 8192;

            float sacc[8][4];
            #pragma unroll
            for (int i = 0; i < 8; i++)
                #pragma unroll
                for (int j = 0; j < 4; j++) sacc[i][j] = 0.f;

            #pragma unroll
            for (int kg = 0; kg < 4; kg++) {
                uint32_t a0[4];
                ldmx4(a0, sQ + swz(wid * 16 + lr, kg * 32 + lc * 16));
                #pragma unroll
                for (int np = 0; np < 4; np++) {
                    uint32_t b4[4];
                    ldmx4(b4, sK + swz(np * 16 + lr, kg * 32 + lc * 16));
                    mma_f16(sacc[np * 2],     a0, b4[0], b4[2]);
                    mma_f16(sacc[np * 2 + 1], a0, b4[1], b4[3]);
                }
            }

            float rm[2] = {-1e30f, -1e30f};
            #pragma unroll
            for (int nt = 0; nt < 8; nt++) {
                #pragma unroll
                for (int j = 0; j < 4; j++) {
                    int jr = j >> 1;
                    int rowg = rowg0 + jr * 8;
                    int colg = kt * 64 + nt * 8 + c2 + (j & 1);
                    float s = sacc[nt][j] * 0.125f;
                    if (colg > rowg) s = -1e30f;
                    sacc[nt][j] = s;
                    rm[jr] = fmaxf(rm[jr], s);
                }
            }
            #pragma unroll
            for (int jr = 0; jr < 2; jr++) {
                rm[jr] = fmaxf(rm[jr], __shfl_xor_sync(0xffffffffu, rm[jr], 1));
                rm[jr] = fmaxf(rm[jr], __shfl_xor_sync(0xffffffffu, rm[jr], 2));
            }
            float sc[2], rs[2] = {0.f, 0.f};
            #pragma unroll
            for (int jr = 0; jr < 2; jr++) {
                float mn = fmaxf(m_i[jr], rm[jr]);
                sc[jr] = __expf(m_i[jr] - mn);
                m_i[jr] = mn;
            }
            #pragma unroll
            for (int nt = 0; nt < 8; nt++) {
                #pragma unroll
                for (int j = 0; j < 4; j++) {
                    float p = __expf(sacc[nt][j] - m_i[j >> 1]);
                    sacc[nt][j] = p;
                    rs[j >> 1] += p;
                }
            }
            #pragma unroll
            for (int jr = 0; jr < 2; jr++) {
                rs[jr] += __shfl_xor_sync(0xffffffffu, rs[jr], 1);
                rs[jr] += __shfl_xor_sync(0xffffffffu, rs[jr], 2);
                l_i[jr] = l_i[jr] * sc[jr] + rs[jr];
            }
            #pragma unroll
            for (int nt = 0; nt < 8; nt++) {
                #pragma unroll
                for (int j = 0; j < 4; j++) oacc[nt][j] *= sc[j >> 1];
            }

            #pragma unroll
            for (int kc = 0; kc < 4; kc++) {
                uint32_t ph[4];
                __half2 p0 = __floats2half2_rn(sacc[2 * kc][0],     sacc[2 * kc][1]);
                __half2 p1 = __floats2half2_rn(sacc[2 * kc][2],     sacc[2 * kc][3]);
                __half2 p2 = __floats2half2_rn(sacc[2 * kc + 1][0], sacc[2 * kc + 1][1]);
                __half2 p3 = __floats2half2_rn(sacc[2 * kc + 1][2], sacc[2 * kc + 1][3]);
                ph[0] = *reinterpret_cast<const uint32_t*>(&p0);
                ph[1] = *reinterpret_cast<const uint32_t*>(&p1);
                ph[2] = *reinterpret_cast<const uint32_t*>(&p2);
                ph[3] = *reinterpret_cast<const uint32_t*>(&p3);
                uint32_t vrow = kc * 16 + ((lane >> 3) & 1) * 8 + (lane & 7);
                #pragma unroll
                for (int dp = 0; dp < 4; dp++) {
                    uint32_t v4[4];
                    ldmx4t(v4, sV + swz(vrow, dp * 32 + (lane >> 4) * 16));
                    mma_f16(oacc[dp * 2],     ph, v4[0], v4[1]);
                    mma_f16(oacc[dp * 2 + 1], ph, v4[2], v4[3]);
                }
            }
        }
        __syncthreads();
    }

    float inv[2] = {1.0f / l_i[0], 1.0f / l_i[1]};
    #pragma unroll
    for (int nt = 0; nt < 8; nt++) {
        #pragma unroll
        for (int jr = 0; jr < 2; jr++) {
            float v0 = oacc[nt][jr * 2 + 0] * inv[jr];
            float v1 = oacc[nt][jr * 2 + 1] * inv[jr];
            __half2 hv = __floats2half2_rn(v0, v1);
            size_t off = (rowbase + rowg0 + jr * 8) * DD + colq + nt * 8 + c2;
            *reinterpret_cast<uint32_t*>(O + off) = *reinterpret_cast<const uint32_t*>(&hv);
        }
    }
}

// ---------------- launch ----------------
extern "C" void kernel_launch(void* const* d_in, const int* in_sizes, int n_in,
                              void* d_out, int out_size) {
    const float* x     = (const float*)d_in[0];
    const float* ln1_g = (const float*)d_in[1];
    const float* ln1_b = (const float*)d_in[2];
    const float* Wq    = (const float*)d_in[3];
    const float* Wk    = (const float*)d_in[4];
    const float* Wv    = (const float*)d_in[5];
    const float* Wo    = (const float*)d_in[6];
    const float* bo    = (const float*)d_in[7];
    const float* ln2_g = (const float*)d_in[8];
    const float* ln2_b = (const float*)d_in[9];
    const float* W1    = (const float*)d_in[10];
    const float* b1    = (const float*)d_in[11];
    const float* W2    = (const float*)d_in[12];
    const float* b2    = (const float*)d_in[13];
    float* out = (float*)d_out;

    float* x2;
    cudaGetSymbolAddress((void**)&x2, g_x2);
    __half *h2, *q, *k, *v, *ctx, *mid;
    cudaGetSymbolAddress((void**)&h2, g_h2);
    cudaGetSymbolAddress((void**)&q, g_q);
    cudaGetSymbolAddress((void**)&k, g_k);
    cudaGetSymbolAddress((void**)&v, g_v);
    cudaGetSymbolAddress((void**)&ctx, g_ctx);
    cudaGetSymbolAddress((void**)&mid, g_mid);

    __half *wq, *wk, *wv, *wo, *w1, *w2;
    cudaGetSymbolAddress((void**)&wq, g_wq);
    cudaGetSymbolAddress((void**)&wk, g_wk);
    cudaGetSymbolAddress((void**)&wv, g_wv);
    cudaGetSymbolAddress((void**)&wo, g_wo);
    cudaGetSymbolAddress((void**)&w1, g_w1);
    cudaGetSymbolAddress((void**)&w2, g_w2);

    static int attr_set = 0;
    if (!attr_set) {
        cudaFuncSetAttribute(attn_mma_kernel, cudaFuncAttributeMaxDynamicSharedMemorySize, AT_SMEM);
        cudaFuncSetAttribute(gemm_qkv,  cudaFuncAttributeMaxDynamicSharedMemorySize, GEMM_SMEM);
        cudaFuncSetAttribute(gemm_f32,  cudaFuncAttributeMaxDynamicSharedMemorySize, GEMM_SMEM);
        cudaFuncSetAttribute(gemm_gelu, cudaFuncAttributeMaxDynamicSharedMemorySize, GEMM_SMEM);
        attr_set = 1;
    }

    const int M = MROWS;
    dim3 tb(32, 8);

    wsplit_f16<<<dim3(DD / 32, DD / 32), tb>>>(Wq, wq, DD, DD);
    wsplit_f16<<<dim3(DD / 32, DD / 32), tb>>>(Wk, wk, DD, DD);
    wsplit_f16<<<dim3(DD / 32, DD / 32), tb>>>(Wv, wv, DD, DD);
    wsplit_f16<<<dim3(DD / 32, DD / 32), tb>>>(Wo, wo, DD, DD);
    wsplit_f16<<<dim3(DFF / 32, DD / 32), tb>>>(W1, w1, DD, DFF);
    wsplit_f16<<<dim3(DD / 32, DFF / 32), tb>>>(W2, w2, DFF, DD);

    ln_f16<<<M, 256>>>(x, ln1_g, ln1_b, h2);

    dim3 gQKV(DD / 128, M / 128, 3);
    gemm_qkv<<<gQKV, 256, GEMM_SMEM>>>(h2, wq, wk, wv, q, k, v);

    dim3 gA(SS / 128, BB * HH);
    attn_mma_kernel<<<gA, 256, AT_SMEM>>>(q, k, v, ctx);

    dim3 gDD(DD / 128, M / 128);
    gemm_f32<<<gDD, 256, GEMM_SMEM>>>(ctx, wo, x2, DD, DD, bo, x);

    ln_f16<<<M, 256>>>(x2, ln2_g, ln2_b, h2);

    dim3 gFF(DFF / 128, M / 128);
    gemm_gelu<<<gFF, 256, GEMM_SMEM>>>(h2, w1, mid, DFF, DD, b1);

    gemm_f32<<<gDD, 256, GEMM_SMEM>>>(mid, w2, out, DD, DFF, b2, x2);
}

// round 11
// speedup vs baseline: 3.5213x; 1.0813x over previous
#include <cuda_runtime.h>
#include <cuda_fp16.h>
#include <math.h>
#include <cstdint>

#define BB 2
#define SS 2048
#define DD 1024
#define HH 16
#define HDIM 64
#define DFF 4096
#define MROWS (BB * SS)

// ---------------- PTX helpers ----------------
__device__ __forceinline__ uint32_t smem_to_u32(const void* p) {
    uint32_t a;
    asm("{ .reg .u64 t; cvta.to.shared.u64 t, %1; cvt.u32.u64 %0, t; }" : "=r"(a) : "l"(p));
    return a;
}
__device__ __forceinline__ void ldmx4(uint32_t* r, uint32_t a) {
    asm volatile("ldmatrix.sync.aligned.m8n8.x4.shared.b16 {%0,%1,%2,%3}, [%4];"
        : "=r"(r[0]), "=r"(r[1]), "=r"(r[2]), "=r"(r[3]) : "r"(a));
}
__device__ __forceinline__ void ldmx4t(uint32_t* r, uint32_t a) {
    asm volatile("ldmatrix.sync.aligned.m8n8.x4.trans.shared.b16 {%0,%1,%2,%3}, [%4];"
        : "=r"(r[0]), "=r"(r[1]), "=r"(r[2]), "=r"(r[3]) : "r"(a));
}
__device__ __forceinline__ void mma_f16(float* c, const uint32_t* a, uint32_t b0, uint32_t b1) {
    asm volatile("mma.sync.aligned.m16n8k16.row.col.f32.f16.f16.f32 "
        "{%0,%1,%2,%3}, {%4,%5,%6,%7}, {%8,%9}, {%0,%1,%2,%3};"
        : "+f"(c[0]), "+f"(c[1]), "+f"(c[2]), "+f"(c[3])
        : "r"(a[0]), "r"(a[1]), "r"(a[2]), "r"(a[3]), "r"(b0), "r"(b1));
}
#define CP_ASYNC16(s, g) asm volatile("cp.async.cg.shared.global [%0], [%1], 16;" :: "r"(s), "l"(g))
#define CP_ASYNC_COMMIT() asm volatile("cp.async.commit_group;" ::: "memory")
#define CP_ASYNC_WAIT2()  asm volatile("cp.async.wait_group 2;" ::: "memory")
#define CP_ASYNC_WAIT1()  asm volatile("cp.async.wait_group 1;" ::: "memory")

__device__ __forceinline__ uint32_t swz(uint32_t row, uint32_t colbyte) {
    return row * 128 + (colbyte ^ ((row & 7) << 4));
}
__device__ __forceinline__ float gelu_exact(float v) {
    return 0.5f * v * (1.0f + erff(v * 0.70710678118654752f));
}

// ---------------- scratch ----------------
__device__ float g_x2[MROWS * DD];
__device__ __half g_h2 [MROWS * DD];
__device__ __half g_q  [MROWS * DD];
__device__ __half g_k  [MROWS * DD];
__device__ __half g_v  [MROWS * DD];
__device__ __half g_ctx[MROWS * DD];
__device__ __half g_mid[(size_t)MROWS * DFF];
__device__ __half g_wq[DD * DD], g_wk[DD * DD], g_wv[DD * DD], g_wo[DD * DD];
__device__ __half g_w1[(size_t)DD * DFF], g_w2[(size_t)DFF * DD];

// ---------------- fused weight transpose (all 6 weights, one launch) ----------------
// block = (32,8). 1D grid of 12288 tiles:
//   [0,4096):  Wq/Wk/Wv/Wo (1024 tiles each), K=N=1024
//   [4096,8192): W1 (K=1024, N=4096) -> bx in [0,128), by in [0,32)
//   [8192,12288): W2 (K=4096, N=1024) -> bx in [0,32), by in [0,128)
__global__ void wsplit_all(const float* __restrict__ Wq, const float* __restrict__ Wk,
                           const float* __restrict__ Wv, const float* __restrict__ Wo,
                           const float* __restrict__ W1, const float* __restrict__ W2,
                           __half* __restrict__ Tq, __half* __restrict__ Tk,
                           __half* __restrict__ Tv, __half* __restrict__ To,
                           __half* __restrict__ T1, __half* __restrict__ T2) {
    int id = blockIdx.x;
    const float* W; __half* T; int K, N, bx, by;
    if (id < 4096) {
        int wi = id >> 10, rem = id & 1023;
        W = (wi == 0) ? Wq : (wi == 1) ? Wk : (wi == 2) ? Wv : Wo;
        T = (wi == 0) ? Tq : (wi == 1) ? Tk : (wi == 2) ? Tv : To;
        K = DD; N = DD; bx = rem & 31; by = rem >> 5;
    } else if (id < 8192) {
        int rem = id - 4096;
        W = W1; T = T1; K = DD; N = DFF; bx = rem & 127; by = rem >> 7;
    } else {
        int rem = id - 8192;
        W = W2; T = T2; K = DFF; N = DD; bx = rem & 31; by = rem >> 5;
    }
    __shared__ float tile[32][33];
    int tx = threadIdx.x, ty = threadIdx.y;
    #pragma unroll
    for (int i = 0; i < 4; i++)
        tile[ty + 8 * i][tx] = W[(size_t)(by * 32 + ty + 8 * i) * N + bx * 32 + tx];
    __syncthreads();
    #pragma unroll
    for (int i = 0; i < 4; i++) {
        float v = tile[tx][ty + 8 * i];
        T[(size_t)(bx * 32 + ty + 8 * i) * K + by * 32 + tx] = __float2half_rn(v);
    }
}

// ---------------- LayerNorm (fp16 out) ----------------
__global__ void ln_f16(const float* __restrict__ x, const float* __restrict__ gamma,
                       const float* __restrict__ beta, __half* __restrict__ y) {
    int row = blockIdx.x, tid = threadIdx.x;
    const float4 v = reinterpret_cast<const float4*>(x + (size_t)row * DD)[tid];
    float s = v.x + v.y + v.z + v.w;
    float sq = v.x * v.x + v.y * v.y + v.z * v.z + v.w * v.w;
    for (int o = 16; o > 0; o >>= 1) {
        s += __shfl_down_sync(0xffffffffu, s, o);
        sq += __shfl_down_sync(0xffffffffu, sq, o);
    }
    __shared__ float ws[8], wq[8];
    int lane = tid & 31, warp = tid >> 5;
    if (lane == 0) { ws[warp] = s; wq[warp] = sq; }
    __syncthreads();
    __shared__ float mu_s, rstd_s;
    if (tid == 0) {
        float ts = 0.f, tq = 0.f;
        #pragma unroll
        for (int i = 0; i < 8; i++) { ts += ws[i]; tq += wq[i]; }
        float mu = ts * (1.0f / DD);
        float var = tq * (1.0f / DD) - mu * mu;
        mu_s = mu; rstd_s = rsqrtf(var + 1e-5f);
    }
    __syncthreads();
    float mu = mu_s, r = rstd_s;
    float4 g4 = reinterpret_cast<const float4*>(gamma)[tid];
    float4 b4 = reinterpret_cast<const float4*>(beta)[tid];
    float o0 = (v.x - mu) * r * g4.x + b4.x;
    float o1 = (v.y - mu) * r * g4.y + b4.y;
    float o2 = (v.z - mu) * r * g4.z + b4.z;
    float o3 = (v.w - mu) * r * g4.w + b4.w;
    __half2 h0 = __floats2half2_rn(o0, o1);
    __half2 h1 = __floats2half2_rn(o2, o3);
    uint2 w = make_uint2(*reinterpret_cast<const uint32_t*>(&h0),
                         *reinterpret_cast<const uint32_t*>(&h1));
    *reinterpret_cast<uint2*>(y + (size_t)row * DD + tid * 4) = w;
}

// ---------------- GEMM core (plain fp16, 4 warps, 64x64 warp tile) ----------------
// CTA 128x128, BK=64, 128 threads. mode 1: fp32+bias+res; 2: fp16+bias+gelu; 3: fp16
__device__ __forceinline__ void cpa_tile(uint32_t sdst, const __half* __restrict__ g,
                                         int K, int r0, int k0, int tid) {
    #pragma unroll
    for (int l = 0; l < 8; l++) {
        int f = tid + 128 * l;
        int row = f >> 3, c = f & 7;
        CP_ASYNC16(sdst + swz(row, c * 16), g + (size_t)(r0 + row) * K + k0 + c * 8);
    }
}

#define STAGE1 (2 * 16384)
#define GEMM_SMEM (3 * STAGE1)

__device__ __forceinline__ void gemm_core(const __half* __restrict__ A,
                                          const __half* __restrict__ B,
                                          float* __restrict__ C,
                                          __half* __restrict__ Ch,
                                          int N, int K,
                                          const float* __restrict__ bias,
                                          const float* __restrict__ res, int mode) {
    extern __shared__ char smem[];
    const uint32_t sb0 = smem_to_u32(smem);
    const int tid = threadIdx.x;
    const int wid = tid >> 5, lane = tid & 31;
    const int wm = wid >> 1, wn = wid & 1;      // 2x2 warp grid, warp tile 64x64
    const int m0 = blockIdx.y * 128, n0 = blockIdx.x * 128;
    const int lr = lane & 15, lc = lane >> 4;

    float acc[4][8][4];
    #pragma unroll
    for (int i = 0; i < 4; i++)
        #pragma unroll
        for (int j = 0; j < 8; j++)
            #pragma unroll
            for (int p = 0; p < 4; p++) acc[i][j][p] = 0.f;

    const int T = K >> 6;
    auto load_tile = [&](int t, int s) {
        uint32_t sb = sb0 + s * STAGE1;
        int k0 = t * 64;
        cpa_tile(sb,         A, K, m0, k0, tid);
        cpa_tile(sb + 16384, B, K, n0, k0, tid);
    };

    load_tile(0, 0);
    CP_ASYNC_COMMIT();
    if (T > 1) load_tile(1, 1);
    CP_ASYNC_COMMIT();

    for (int t = 0; t < T; t++) {
        if (t + 2 < T) load_tile(t + 2, (t + 2) % 3);
        CP_ASYNC_COMMIT();
        CP_ASYNC_WAIT2();
        __syncthreads();

        const uint32_t sb = sb0 + (t % 3) * STAGE1;
        const uint32_t sA = sb, sB = sb + 16384;
        #pragma unroll
        for (int kg = 0; kg < 4; kg++) {
            uint32_t a0[4][4], b4[4][4];
            #pragma unroll
            for (int mt = 0; mt < 4; mt++)
                ldmx4(a0[mt], sA + swz(wm * 64 + mt * 16 + lr, kg * 32 + lc * 16));
            #pragma unroll
            for (int np = 0; np < 4; np++)
                ldmx4(b4[np], sB + swz(wn * 64 + np * 16 + lr, kg * 32 + lc * 16));
            #pragma unroll
            for (int mt = 0; mt < 4; mt++) {
                #pragma unroll
                for (int np = 0; np < 4; np++) {
                    mma_f16(acc[mt][np * 2 + 0], a0[mt], b4[np][0], b4[np][2]);
                    mma_f16(acc[mt][np * 2 + 1], a0[mt], b4[np][1], b4[np][3]);
                }
            }
        }
        __syncthreads();
    }

    #pragma unroll
    for (int mt = 0; mt < 4; mt++) {
        #pragma unroll
        for (int nt = 0; nt < 8; nt++) {
            int r0 = m0 + wm * 64 + mt * 16 + (lane >> 2);
            int c0 = n0 + wn * 64 + nt * 8 + (lane & 3) * 2;
            float bv0 = 0.f, bv1 = 0.f;
            if (mode == 1 || mode == 2) { bv0 = bias[c0]; bv1 = bias[c0 + 1]; }
            #pragma unroll
            for (int half = 0; half < 2; half++) {
                int r = r0 + half * 8;
                float v0 = acc[mt][nt][half * 2 + 0] + bv0;
                float v1 = acc[mt][nt][half * 2 + 1] + bv1;
                if (mode == 3) {
                    __half2 hv = __floats2half2_rn(v0, v1);
                    *reinterpret_cast<uint32_t*>(Ch + (size_t)r * N + c0) =
                        *reinterpret_cast<const uint32_t*>(&hv);
                } else if (mode == 2) {
                    v0 = gelu_exact(v0); v1 = gelu_exact(v1);
                    __half2 hv = __floats2half2_rn(v0, v1);
                    *reinterpret_cast<uint32_t*>(Ch + (size_t)r * N + c0) =
                        *reinterpret_cast<const uint32_t*>(&hv);
                } else {
                    float2 rr = *(const float2*)(res + (size_t)r * N + c0);
                    *(float2*)(C + (size_t)r * N + c0) = make_float2(v0 + rr.x, v1 + rr.y);
                }
            }
        }
    }
}

__global__ void __launch_bounds__(128, 2)
gemm_qkv(const __half* __restrict__ A,
         const __half* __restrict__ wq, const __half* __restrict__ wk,
         const __half* __restrict__ wv,
         __half* __restrict__ q, __half* __restrict__ k, __half* __restrict__ v) {
    const __half* B = (blockIdx.z == 0) ? wq : (blockIdx.z == 1) ? wk : wv;
    __half* Ch = (blockIdx.z == 0) ? q : (blockIdx.z == 1) ? k : v;
    gemm_core(A, B, nullptr, Ch, DD, DD, nullptr, nullptr, 3);
}
__global__ void __launch_bounds__(128, 2)
gemm_f32(const __half* __restrict__ A, const __half* __restrict__ B,
         float* __restrict__ C, int N, int K,
         const float* __restrict__ bias, const float* __restrict__ res) {
    gemm_core(A, B, C, nullptr, N, K, bias, res, 1);
}
__global__ void __launch_bounds__(128, 2)
gemm_gelu(const __half* __restrict__ A, const __half* __restrict__ B,
          __half* __restrict__ Cf, int N, int K, const float* __restrict__ bias) {
    gemm_core(A, B, nullptr, Cf, N, K, bias, nullptr, 2);
}

// ---------------- Flash attention plain fp16 (unchanged from R10) ----------------
#define AT_STAGE 16384
#define AT_SMEM (16384 + 2 * AT_STAGE)

__global__ void __launch_bounds__(256, 2)
attn_mma_kernel(const __half* __restrict__ q, const __half* __restrict__ k,
                const __half* __restrict__ v, __half* __restrict__ O) {
    extern __shared__ char smem[];
    const uint32_t sb = smem_to_u32(smem);
    const uint32_t sQ = sb;
    const int tid = threadIdx.x, wid = tid >> 5, lane = tid & 31;
    const int qt = blockIdx.x;
    const int h = blockIdx.y & 15, b = blockIdx.y >> 4;
    const size_t rowbase = (size_t)b * SS;
    const int colq = h * HDIM;

    #pragma unroll
    for (int l = 0; l < 4; l++) {
        int f = tid + 256 * l;
        int row = f >> 3, c = f & 7;
        CP_ASYNC16(sQ + swz(row, c * 16),
                   q + (rowbase + qt * 128 + row) * DD + colq + c * 8);
    }
    CP_ASYNC_COMMIT();

    auto load_kv = [&](int kt, int s) {
        uint32_t st = sb + 16384 + s * AT_STAGE;
        #pragma unroll
        for (int l = 0; l < 2; l++) {
            int f = tid + 256 * l;
            int row = f >> 3, c = f & 7;
            size_t g = (rowbase + kt * 64 + row) * DD + colq + c * 8;
            uint32_t o = swz(row, c * 16);
            CP_ASYNC16(st + o,        k + g);
            CP_ASYNC16(st + 8192 + o, v + g);
        }
    };
    load_kv(0, 0);
    CP_ASYNC_COMMIT();

    const int nkt = 2 * qt + 2;
    const int ktmax_w = (qt * 128 + wid * 16 + 15) >> 6;
    const int lr = lane & 15, lc = lane >> 4;
    const int r0l = lane >> 2;
    const int c2 = (lane & 3) * 2;
    const int rowg0 = qt * 128 + wid * 16 + r0l;

    float m_i[2] = {-1e30f, -1e30f}, l_i[2] = {0.f, 0.f};
    float oacc[8][4];
    #pragma unroll
    for (int i = 0; i < 8; i++)
        #pragma unroll
        for (int j = 0; j < 4; j++) oacc[i][j] = 0.f;

    for (int kt = 0; kt < nkt; kt++) {
        if (kt + 1 < nkt) load_kv(kt + 1, (kt + 1) & 1);
        CP_ASYNC_COMMIT();
        CP_ASYNC_WAIT1();
        __syncthreads();

        if (kt <= ktmax_w) {
            uint32_t st = sb + 16384 + (kt & 1) * AT_STAGE;
            uint32_t sK = st, sV = st + 8192;

            float sacc[8][4];
            #pragma unroll
            for (int i = 0; i < 8; i++)
                #pragma unroll
                for (int j = 0; j < 4; j++) sacc[i][j] = 0.f;

            #pragma unroll
            for (int kg = 0; kg < 4; kg++) {
                uint32_t a0[4];
                ldmx4(a0, sQ + swz(wid * 16 + lr, kg * 32 + lc * 16));
                #pragma unroll
                for (int np = 0; np < 4; np++) {
                    uint32_t b4[4];
                    ldmx4(b4, sK + swz(np * 16 + lr, kg * 32 + lc * 16));
                    mma_f16(sacc[np * 2],     a0, b4[0], b4[2]);
                    mma_f16(sacc[np * 2 + 1], a0, b4[1], b4[3]);
                }
            }

            float rm[2] = {-1e30f, -1e30f};
            #pragma unroll
            for (int nt = 0; nt < 8; nt++) {
                #pragma unroll
                for (int j = 0; j < 4; j++) {
                    int jr = j >> 1;
                    int rowg = rowg0 + jr * 8;
                    int colg = kt * 64 + nt * 8 + c2 + (j & 1);
                    float s = sacc[nt][j] * 0.125f;
                    if (colg > rowg) s = -1e30f;
                    sacc[nt][j] = s;
                    rm[jr] = fmaxf(rm[jr], s);
                }
            }
            #pragma unroll
            for (int jr = 0; jr < 2; jr++) {
                rm[jr] = fmaxf(rm[jr], __shfl_xor_sync(0xffffffffu, rm[jr], 1));
                rm[jr] = fmaxf(rm[jr], __shfl_xor_sync(0xffffffffu, rm[jr], 2));
            }
            float sc[2], rs[2] = {0.f, 0.f};
            #pragma unroll
            for (int jr = 0; jr < 2; jr++) {
                float mn = fmaxf(m_i[jr], rm[jr]);
                sc[jr] = __expf(m_i[jr] - mn);
                m_i[jr] = mn;
            }
            #pragma unroll
            for (int nt = 0; nt < 8; nt++) {
                #pragma unroll
                for (int j = 0; j < 4; j++) {
                    float p = __expf(sacc[nt][j] - m_i[j >> 1]);
                    sacc[nt][j] = p;
                    rs[j >> 1] += p;
                }
            }
            #pragma unroll
            for (int jr = 0; jr < 2; jr++) {
                rs[jr] += __shfl_xor_sync(0xffffffffu, rs[jr], 1);
                rs[jr] += __shfl_xor_sync(0xffffffffu, rs[jr], 2);
                l_i[jr] = l_i[jr] * sc[jr] + rs[jr];
            }
            #pragma unroll
            for (int nt = 0; nt < 8; nt++) {
                #pragma unroll
                for (int j = 0; j < 4; j++) oacc[nt][j] *= sc[j >> 1];
            }

            #pragma unroll
            for (int kc = 0; kc < 4; kc++) {
                uint32_t ph[4];
                __half2 p0 = __floats2half2_rn(sacc[2 * kc][0],     sacc[2 * kc][1]);
                __half2 p1 = __floats2half2_rn(sacc[2 * kc][2],     sacc[2 * kc][3]);
                __half2 p2 = __floats2half2_rn(sacc[2 * kc + 1][0], sacc[2 * kc + 1][1]);
                __half2 p3 = __floats2half2_rn(sacc[2 * kc + 1][2], sacc[2 * kc + 1][3]);
                ph[0] = *reinterpret_cast<const uint32_t*>(&p0);
                ph[1] = *reinterpret_cast<const uint32_t*>(&p1);
                ph[2] = *reinterpret_cast<const uint32_t*>(&p2);
                ph[3] = *reinterpret_cast<const uint32_t*>(&p3);
                uint32_t vrow = kc * 16 + ((lane >> 3) & 1) * 8 + (lane & 7);
                #pragma unroll
                for (int dp = 0; dp < 4; dp++) {
                    uint32_t v4[4];
                    ldmx4t(v4, sV + swz(vrow, dp * 32 + (lane >> 4) * 16));
                    mma_f16(oacc[dp * 2],     ph, v4[0], v4[1]);
                    mma_f16(oacc[dp * 2 + 1], ph, v4[2], v4[3]);
                }
            }
        }
        __syncthreads();
    }

    float inv[2] = {1.0f / l_i[0], 1.0f / l_i[1]};
    #pragma unroll
    for (int nt = 0; nt < 8; nt++) {
        #pragma unroll
        for (int jr = 0; jr < 2; jr++) {
            float v0 = oacc[nt][jr * 2 + 0] * inv[jr];
            float v1 = oacc[nt][jr * 2 + 1] * inv[jr];
            __half2 hv = __floats2half2_rn(v0, v1);
            size_t off = (rowbase + rowg0 + jr * 8) * DD + colq + nt * 8 + c2;
            *reinterpret_cast<uint32_t*>(O + off) = *reinterpret_cast<const uint32_t*>(&hv);
        }
    }
}

// ---------------- launch ----------------
extern "C" void kernel_launch(void* const* d_in, const int* in_sizes, int n_in,
                              void* d_out, int out_size) {
    const float* x     = (const float*)d_in[0];
    const float* ln1_g = (const float*)d_in[1];
    const float* ln1_b = (const float*)d_in[2];
    const float* Wq    = (const float*)d_in[3];
    const float* Wk    = (const float*)d_in[4];
    const float* Wv    = (const float*)d_in[5];
    const float* Wo    = (const float*)d_in[6];
    const float* bo    = (const float*)d_in[7];
    const float* ln2_g = (const float*)d_in[8];
    const float* ln2_b = (const float*)d_in[9];
    const float* W1    = (const float*)d_in[10];
    const float* b1    = (const float*)d_in[11];
    const float* W2    = (const float*)d_in[12];
    const float* b2    = (const float*)d_in[13];
    float* out = (float*)d_out;

    float* x2;
    cudaGetSymbolAddress((void**)&x2, g_x2);
    __half *h2, *q, *k, *v, *ctx, *mid;
    cudaGetSymbolAddress((void**)&h2, g_h2);
    cudaGetSymbolAddress((void**)&q, g_q);
    cudaGetSymbolAddress((void**)&k, g_k);
    cudaGetSymbolAddress((void**)&v, g_v);
    cudaGetSymbolAddress((void**)&ctx, g_ctx);
    cudaGetSymbolAddress((void**)&mid, g_mid);

    __half *wq, *wk, *wv, *wo, *w1, *w2;
    cudaGetSymbolAddress((void**)&wq, g_wq);
    cudaGetSymbolAddress((void**)&wk, g_wk);
    cudaGetSymbolAddress((void**)&wv, g_wv);
    cudaGetSymbolAddress((void**)&wo, g_wo);
    cudaGetSymbolAddress((void**)&w1, g_w1);
    cudaGetSymbolAddress((void**)&w2, g_w2);

    static int attr_set = 0;
    if (!attr_set) {
        cudaFuncSetAttribute(attn_mma_kernel, cudaFuncAttributeMaxDynamicSharedMemorySize, AT_SMEM);
        cudaFuncSetAttribute(gemm_qkv,  cudaFuncAttributeMaxDynamicSharedMemorySize, GEMM_SMEM);
        cudaFuncSetAttribute(gemm_f32,  cudaFuncAttributeMaxDynamicSharedMemorySize, GEMM_SMEM);
        cudaFuncSetAttribute(gemm_gelu, cudaFuncAttributeMaxDynamicSharedMemorySize, GEMM_SMEM);
        attr_set = 1;
    }

    const int M = MROWS;

    // 1. all weight transposes in ONE launch
    wsplit_all<<<12288, dim3(32, 8)>>>(Wq, Wk, Wv, Wo, W1, W2, wq, wk, wv, wo, w1, w2);

    // 2. LN1
    ln_f16<<<M, 256>>>(x, ln1_g, ln1_b, h2);

    // 3. QKV
    dim3 gQKV(DD / 128, M / 128, 3);
    gemm_qkv<<<gQKV, 128, GEMM_SMEM>>>(h2, wq, wk, wv, q, k, v);

    // 4. attention
    dim3 gA(SS / 128, BB * HH);
    attn_mma_kernel<<<gA, 256, AT_SMEM>>>(q, k, v, ctx);

    // 5. Wo + bias + residual
    dim3 gDD(DD / 128, M / 128);
    gemm_f32<<<gDD, 128, GEMM_SMEM>>>(ctx, wo, x2, DD, DD, bo, x);

    // 6. LN2
    ln_f16<<<M, 256>>>(x2, ln2_g, ln2_b, h2);

    // 7. MLP1 + GELU
    dim3 gFF(DFF / 128, M / 128);
    gemm_gelu<<<gFF, 128, GEMM_SMEM>>>(h2, w1, mid, DFF, DD, b1);

    // 8. MLP2 + bias + residual
    gemm_f32<<<gDD, 128, GEMM_SMEM>>>(mid, w2, out, DD, DFF, b2, x2);
}

// round 13
// speedup vs baseline: 3.5791x; 1.0164x over previous
#include <cuda_runtime.h>
#include <cuda_fp16.h>
#include <math.h>
#include <cstdint>

#define BB 2
#define SS 2048
#define DD 1024
#define HH 16
#define HDIM 64
#define DFF 4096
#define MROWS (BB * SS)

// ---------------- PTX helpers ----------------
__device__ __forceinline__ uint32_t smem_to_u32(const void* p) {
    uint32_t a;
    asm("{ .reg .u64 t; cvta.to.shared.u64 t, %1; cvt.u32.u64 %0, t; }" : "=r"(a) : "l"(p));
    return a;
}
__device__ __forceinline__ void ldmx4(uint32_t* r, uint32_t a) {
    asm volatile("ldmatrix.sync.aligned.m8n8.x4.shared.b16 {%0,%1,%2,%3}, [%4];"
        : "=r"(r[0]), "=r"(r[1]), "=r"(r[2]), "=r"(r[3]) : "r"(a));
}
__device__ __forceinline__ void ldmx4t(uint32_t* r, uint32_t a) {
    asm volatile("ldmatrix.sync.aligned.m8n8.x4.trans.shared.b16 {%0,%1,%2,%3}, [%4];"
        : "=r"(r[0]), "=r"(r[1]), "=r"(r[2]), "=r"(r[3]) : "r"(a));
}
__device__ __forceinline__ void mma_f16(float* c, const uint32_t* a, uint32_t b0, uint32_t b1) {
    asm volatile("mma.sync.aligned.m16n8k16.row.col.f32.f16.f16.f32 "
        "{%0,%1,%2,%3}, {%4,%5,%6,%7}, {%8,%9}, {%0,%1,%2,%3};"
        : "+f"(c[0]), "+f"(c[1]), "+f"(c[2]), "+f"(c[3])
        : "r"(a[0]), "r"(a[1]), "r"(a[2]), "r"(a[3]), "r"(b0), "r"(b1));
}
#define CP_ASYNC16(s, g) asm volatile("cp.async.cg.shared.global [%0], [%1], 16;" :: "r"(s), "l"(g))
#define CP_ASYNC_COMMIT() asm volatile("cp.async.commit_group;" ::: "memory")
#define CP_ASYNC_WAIT1()  asm volatile("cp.async.wait_group 1;" ::: "memory")

__device__ __forceinline__ uint32_t swz(uint32_t row, uint32_t colbyte) {
    return row * 128 + (colbyte ^ ((row & 7) << 4));
}
__device__ __forceinline__ float gelu_exact(float v) {
    return 0.5f * v * (1.0f + erff(v * 0.70710678118654752f));
}

// ---------------- scratch ----------------
__device__ float g_x2[MROWS * DD];
__device__ __half g_h2 [MROWS * DD];
__device__ __half g_q  [MROWS * DD];
__device__ __half g_k  [MROWS * DD];
__device__ __half g_v  [MROWS * DD];
__device__ __half g_ctx[MROWS * DD];
__device__ __half g_mid[(size_t)MROWS * DFF];
__device__ __half g_wq[DD * DD], g_wk[DD * DD], g_wv[DD * DD], g_wo[DD * DD];
__device__ __half g_w1[(size_t)DD * DFF], g_w2[(size_t)DFF * DD];

// ---------------- fused weight transpose (all 6 weights, one launch) ----------------
__global__ void wsplit_all(const float* __restrict__ Wq, const float* __restrict__ Wk,
                           const float* __restrict__ Wv, const float* __restrict__ Wo,
                           const float* __restrict__ W1, const float* __restrict__ W2,
                           __half* __restrict__ Tq, __half* __restrict__ Tk,
                           __half* __restrict__ Tv, __half* __restrict__ To,
                           __half* __restrict__ T1, __half* __restrict__ T2) {
    int id = blockIdx.x;
    const float* W; __half* T; int K, N, bx, by;
    if (id < 4096) {
        int wi = id >> 10, rem = id & 1023;
        W = (wi == 0) ? Wq : (wi == 1) ? Wk : (wi == 2) ? Wv : Wo;
        T = (wi == 0) ? Tq : (wi == 1) ? Tk : (wi == 2) ? Tv : To;
        K = DD; N = DD; bx = rem & 31; by = rem >> 5;
    } else if (id < 8192) {
        int rem = id - 4096;
        W = W1; T = T1; K = DD; N = DFF; bx = rem & 127; by = rem >> 7;
    } else {
        int rem = id - 8192;
        W = W2; T = T2; K = DFF; N = DD; bx = rem & 31; by = rem >> 5;
    }
    __shared__ float tile[32][33];
    int tx = threadIdx.x, ty = threadIdx.y;
    #pragma unroll
    for (int i = 0; i < 4; i++)
        tile[ty + 8 * i][tx] = W[(size_t)(by * 32 + ty + 8 * i) * N + bx * 32 + tx];
    __syncthreads();
    #pragma unroll
    for (int i = 0; i < 4; i++) {
        float v = tile[tx][ty + 8 * i];
        T[(size_t)(bx * 32 + ty + 8 * i) * K + by * 32 + tx] = __float2half_rn(v);
    }
}

// ---------------- LayerNorm (fp16 out) ----------------
__global__ void ln_f16(const float* __restrict__ x, const float* __restrict__ gamma,
                       const float* __restrict__ beta, __half* __restrict__ y) {
    int row = blockIdx.x, tid = threadIdx.x;
    const float4 v = reinterpret_cast<const float4*>(x + (size_t)row * DD)[tid];
    float s = v.x + v.y + v.z + v.w;
    float sq = v.x * v.x + v.y * v.y + v.z * v.z + v.w * v.w;
    for (int o = 16; o > 0; o >>= 1) {
        s += __shfl_down_sync(0xffffffffu, s, o);
        sq += __shfl_down_sync(0xffffffffu, sq, o);
    }
    __shared__ float ws[8], wq[8];
    int lane = tid & 31, warp = tid >> 5;
    if (lane == 0) { ws[warp] = s; wq[warp] = sq; }
    __syncthreads();
    __shared__ float mu_s, rstd_s;
    if (tid == 0) {
        float ts = 0.f, tq = 0.f;
        #pragma unroll
        for (int i = 0; i < 8; i++) { ts += ws[i]; tq += wq[i]; }
        float mu = ts * (1.0f / DD);
        float var = tq * (1.0f / DD) - mu * mu;
        mu_s = mu; rstd_s = rsqrtf(var + 1e-5f);
    }
    __syncthreads();
    float mu = mu_s, r = rstd_s;
    float4 g4 = reinterpret_cast<const float4*>(gamma)[tid];
    float4 b4 = reinterpret_cast<const float4*>(beta)[tid];
    float o0 = (v.x - mu) * r * g4.x + b4.x;
    float o1 = (v.y - mu) * r * g4.y + b4.y;
    float o2 = (v.z - mu) * r * g4.z + b4.z;
    float o3 = (v.w - mu) * r * g4.w + b4.w;
    __half2 h0 = __floats2half2_rn(o0, o1);
    __half2 h1 = __floats2half2_rn(o2, o3);
    uint2 w = make_uint2(*reinterpret_cast<const uint32_t*>(&h0),
                         *reinterpret_cast<const uint32_t*>(&h1));
    *reinterpret_cast<uint2*>(y + (size_t)row * DD + tid * 4) = w;
}

// ---------------- GEMM core (fp16, 4 warps, 64x64 warp tile, frag pipeline) ----------------
__device__ __forceinline__ void cpa_tile(uint32_t sdst, const __half* __restrict__ g,
                                         int K, int r0, int k0, int tid) {
    #pragma unroll
    for (int l = 0; l < 8; l++) {
        int f = tid + 128 * l;
        int row = f >> 3, c = f & 7;
        CP_ASYNC16(sdst + swz(row, c * 16), g + (size_t)(r0 + row) * K + k0 + c * 8);
    }
}

#define STAGE1 (2 * 16384)
#define GEMM_SMEM (3 * STAGE1)

__device__ __forceinline__ void gemm_core(const __half* __restrict__ A,
                                          const __half* __restrict__ B,
                                          float* __restrict__ C,
                                          __half* __restrict__ Ch,
                                          int N, int K,
                                          const float* __restrict__ bias,
                                          const float* __restrict__ res, int mode) {
    extern __shared__ char smem[];
    const uint32_t sb0 = smem_to_u32(smem);
    const int tid = threadIdx.x;
    const int wid = tid >> 5, lane = tid & 31;
    const int wm = wid >> 1, wn = wid & 1;      // 2x2 warp grid, warp tile 64x64
    const int m0 = blockIdx.y * 128, n0 = blockIdx.x * 128;
    const int lr = lane & 15, lc = lane >> 4;

    float acc[4][8][4];
    #pragma unroll
    for (int i = 0; i < 4; i++)
        #pragma unroll
        for (int j = 0; j < 8; j++)
            #pragma unroll
            for (int p = 0; p < 4; p++) acc[i][j][p] = 0.f;

    const int T = K >> 6;
    auto load_tile = [&](int t, int s) {
        uint32_t sb = sb0 + s * STAGE1;
        int k0 = t * 64;
        cpa_tile(sb,         A, K, m0, k0, tid);
        cpa_tile(sb + 16384, B, K, n0, k0, tid);
    };

    load_tile(0, 0);
    CP_ASYNC_COMMIT();
    load_tile(1, 1);
    CP_ASYNC_COMMIT();

    uint32_t af[2][4][4], bf[2][4][4];

    for (int t = 0; t < T; t++) {
        CP_ASYNC_WAIT1();          // tile t complete (t+1 may be in flight)
        __syncthreads();           // all warps done reading stage (t-1)%3, data of t visible
        if (t + 2 < T) { load_tile(t + 2, (t + 2) % 3); CP_ASYNC_COMMIT(); }

        const uint32_t sb = sb0 + (t % 3) * STAGE1;
        const uint32_t sA = sb, sB = sb + 16384;

        // prime kg=0 fragments
        #pragma unroll
        for (int mt = 0; mt < 4; mt++)
            ldmx4(af[0][mt], sA + swz(wm * 64 + mt * 16 + lr, lc * 16));
        #pragma unroll
        for (int np = 0; np < 4; np++)
            ldmx4(bf[0][np], sB + swz(wn * 64 + np * 16 + lr, lc * 16));

        #pragma unroll
        for (int kg = 0; kg < 4; kg++) {
            const int cur = kg & 1, nxt = cur ^ 1;
            if (kg < 3) {
                #pragma unroll
                for (int mt = 0; mt < 4; mt++)
                    ldmx4(af[nxt][mt], sA + swz(wm * 64 + mt * 16 + lr, (kg + 1) * 32 + lc * 16));
                #pragma unroll
                for (int np = 0; np < 4; np++)
                    ldmx4(bf[nxt][np], sB + swz(wn * 64 + np * 16 + lr, (kg + 1) * 32 + lc * 16));
            }
            #pragma unroll
            for (int mt = 0; mt < 4; mt++) {
                #pragma unroll
                for (int np = 0; np < 4; np++) {
                    mma_f16(acc[mt][np * 2 + 0], af[cur][mt], bf[cur][np][0], bf[cur][np][2]);
                    mma_f16(acc[mt][np * 2 + 1], af[cur][mt], bf[cur][np][1], bf[cur][np][3]);
                }
            }
        }
    }

    #pragma unroll
    for (int mt = 0; mt < 4; mt++) {
        #pragma unroll
        for (int nt = 0; nt < 8; nt++) {
            int r0 = m0 + wm * 64 + mt * 16 + (lane >> 2);
            int c0 = n0 + wn * 64 + nt * 8 + (lane & 3) * 2;
            float bv0 = 0.f, bv1 = 0.f;
            if (mode == 1 || mode == 2) { bv0 = bias[c0]; bv1 = bias[c0 + 1]; }
            #pragma unroll
            for (int half = 0; half < 2; half++) {
                int r = r0 + half * 8;
                float v0 = acc[mt][nt][half * 2 + 0] + bv0;
                float v1 = acc[mt][nt][half * 2 + 1] + bv1;
                if (mode == 3) {
                    __half2 hv = __floats2half2_rn(v0, v1);
                    *reinterpret_cast<uint32_t*>(Ch + (size_t)r * N + c0) =
                        *reinterpret_cast<const uint32_t*>(&hv);
                } else if (mode == 2) {
                    v0 = gelu_exact(v0); v1 = gelu_exact(v1);
                    __half2 hv = __floats2half2_rn(v0, v1);
                    *reinterpret_cast<uint32_t*>(Ch + (size_t)r * N + c0) =
                        *reinterpret_cast<const uint32_t*>(&hv);
                } else {
                    float2 rr = *(const float2*)(res + (size_t)r * N + c0);
                    *(float2*)(C + (size_t)r * N + c0) = make_float2(v0 + rr.x, v1 + rr.y);
                }
            }
        }
    }
}

__global__ void __launch_bounds__(128, 2)
gemm_qkv(const __half* __restrict__ A,
         const __half* __restrict__ wq, const __half* __restrict__ wk,
         const __half* __restrict__ wv,
         __half* __restrict__ q, __half* __restrict__ k, __half* __restrict__ v) {
    const __half* B = (blockIdx.z == 0) ? wq : (blockIdx.z == 1) ? wk : wv;
    __half* Ch = (blockIdx.z == 0) ? q : (blockIdx.z == 1) ? k : v;
    gemm_core(A, B, nullptr, Ch, DD, DD, nullptr, nullptr, 3);
}
__global__ void __launch_bounds__(128, 2)
gemm_f32(const __half* __restrict__ A, const __half* __restrict__ B,
         float* __restrict__ C, int N, int K,
         const float* __restrict__ bias, const float* __restrict__ res) {
    gemm_core(A, B, C, nullptr, N, K, bias, res, 1);
}
__global__ void __launch_bounds__(128, 2)
gemm_gelu(const __half* __restrict__ A, const __half* __restrict__ B,
          __half* __restrict__ Cf, int N, int K, const float* __restrict__ bias) {
    gemm_core(A, B, nullptr, Cf, N, K, bias, nullptr, 2);
}

// ---------------- Flash attention plain fp16 (unchanged) ----------------
#define AT_STAGE 16384
#define AT_SMEM (16384 + 2 * AT_STAGE)
#define CP_ASYNC_WAIT1A() asm volatile("cp.async.wait_group 1;" ::: "memory")

__global__ void __launch_bounds__(256, 2)
attn_mma_kernel(const __half* __restrict__ q, const __half* __restrict__ k,
                const __half* __restrict__ v, __half* __restrict__ O) {
    extern __shared__ char smem[];
    const uint32_t sb = smem_to_u32(smem);
    const uint32_t sQ = sb;
    const int tid = threadIdx.x, wid = tid >> 5, lane = tid & 31;
    const int qt = blockIdx.x;
    const int h = blockIdx.y & 15, b = blockIdx.y >> 4;
    const size_t rowbase = (size_t)b * SS;
    const int colq = h * HDIM;

    #pragma unroll
    for (int l = 0; l < 4; l++) {
        int f = tid + 256 * l;
        int row = f >> 3, c = f & 7;
        CP_ASYNC16(sQ + swz(row, c * 16),
                   q + (rowbase + qt * 128 + row) * DD + colq + c * 8);
    }
    CP_ASYNC_COMMIT();

    auto load_kv = [&](int kt, int s) {
        uint32_t st = sb + 16384 + s * AT_STAGE;
        #pragma unroll
        for (int l = 0; l < 2; l++) {
            int f = tid + 256 * l;
            int row = f >> 3, c = f & 7;
            size_t g = (rowbase + kt * 64 + row) * DD + colq + c * 8;
            uint32_t o = swz(row, c * 16);
            CP_ASYNC16(st + o,        k + g);
            CP_ASYNC16(st + 8192 + o, v + g);
        }
    };
    load_kv(0, 0);
    CP_ASYNC_COMMIT();

    const int nkt = 2 * qt + 2;
    const int ktmax_w = (qt * 128 + wid * 16 + 15) >> 6;
    const int lr = lane & 15, lc = lane >> 4;
    const int r0l = lane >> 2;
    const int c2 = (lane & 3) * 2;
    const int rowg0 = qt * 128 + wid * 16 + r0l;

    float m_i[2] = {-1e30f, -1e30f}, l_i[2] = {0.f, 0.f};
    float oacc[8][4];
    #pragma unroll
    for (int i = 0; i < 8; i++)
        #pragma unroll
        for (int j = 0; j < 4; j++) oacc[i][j] = 0.f;

    for (int kt = 0; kt < nkt; kt++) {
        if (kt + 1 < nkt) load_kv(kt + 1, (kt + 1) & 1);
        CP_ASYNC_COMMIT();
        CP_ASYNC_WAIT1A();
        __syncthreads();

        if (kt <= ktmax_w) {
            uint32_t st = sb + 16384 + (kt & 1) * AT_STAGE;
            uint32_t sK = st, sV = st + 8192;

            float sacc[8][4];
            #pragma unroll
            for (int i = 0; i < 8; i++)
                #pragma unroll
                for (int j = 0; j < 4; j++) sacc[i][j] = 0.f;

            #pragma unroll
            for (int kg = 0; kg < 4; kg++) {
                uint32_t a0[4];
                ldmx4(a0, sQ + swz(wid * 16 + lr, kg * 32 + lc * 16));
                #pragma unroll
                for (int np = 0; np < 4; np++) {
                    uint32_t b4[4];
                    ldmx4(b4, sK + swz(np * 16 + lr, kg * 32 + lc * 16));
                    mma_f16(sacc[np * 2],     a0, b4[0], b4[2]);
                    mma_f16(sacc[np * 2 + 1], a0, b4[1], b4[3]);
                }
            }

            float rm[2] = {-1e30f, -1e30f};
            #pragma unroll
            for (int nt = 0; nt < 8; nt++) {
                #pragma unroll
                for (int j = 0; j < 4; j++) {
                    int jr = j >> 1;
                    int rowg = rowg0 + jr * 8;
                    int colg = kt * 64 + nt * 8 + c2 + (j & 1);
                    float s = sacc[nt][j] * 0.125f;
                    if (colg > rowg) s = -1e30f;
                    sacc[nt][j] = s;
                    rm[jr] = fmaxf(rm[jr], s);
                }
            }
            #pragma unroll
            for (int jr = 0; jr < 2; jr++) {
                rm[jr] = fmaxf(rm[jr], __shfl_xor_sync(0xffffffffu, rm[jr], 1));
                rm[jr] = fmaxf(rm[jr], __shfl_xor_sync(0xffffffffu, rm[jr], 2));
            }
            float sc[2], rs[2] = {0.f, 0.f};
            #pragma unroll
            for (int jr = 0; jr < 2; jr++) {
                float mn = fmaxf(m_i[jr], rm[jr]);
                sc[jr] = __expf(m_i[jr] - mn);
                m_i[jr] = mn;
            }
            #pragma unroll
            for (int nt = 0; nt < 8; nt++) {
                #pragma unroll
                for (int j = 0; j < 4; j++) {
                    float p = __expf(sacc[nt][j] - m_i[j >> 1]);
                    sacc[nt][j] = p;
                    rs[j >> 1] += p;
                }
            }
            #pragma unroll
            for (int jr = 0; jr < 2; jr++) {
                rs[jr] += __shfl_xor_sync(0xffffffffu, rs[jr], 1);
                rs[jr] += __shfl_xor_sync(0xffffffffu, rs[jr], 2);
                l_i[jr] = l_i[jr] * sc[jr] + rs[jr];
            }
            #pragma unroll
            for (int nt = 0; nt < 8; nt++) {
                #pragma unroll
                for (int j = 0; j < 4; j++) oacc[nt][j] *= sc[j >> 1];
            }

            #pragma unroll
            for (int kc = 0; kc < 4; kc++) {
                uint32_t ph[4];
                __half2 p0 = __floats2half2_rn(sacc[2 * kc][0],     sacc[2 * kc][1]);
                __half2 p1 = __floats2half2_rn(sacc[2 * kc][2],     sacc[2 * kc][3]);
                __half2 p2 = __floats2half2_rn(sacc[2 * kc + 1][0], sacc[2 * kc + 1][1]);
                __half2 p3 = __floats2half2_rn(sacc[2 * kc + 1][2], sacc[2 * kc + 1][3]);
                ph[0] = *reinterpret_cast<const uint32_t*>(&p0);
                ph[1] = *reinterpret_cast<const uint32_t*>(&p1);
                ph[2] = *reinterpret_cast<const uint32_t*>(&p2);
                ph[3] = *reinterpret_cast<const uint32_t*>(&p3);
                uint32_t vrow = kc * 16 + ((lane >> 3) & 1) * 8 + (lane & 7);
                #pragma unroll
                for (int dp = 0; dp < 4; dp++) {
                    uint32_t v4[4];
                    ldmx4t(v4, sV + swz(vrow, dp * 32 + (lane >> 4) * 16));
                    mma_f16(oacc[dp * 2],     ph, v4[0], v4[1]);
                    mma_f16(oacc[dp * 2 + 1], ph, v4[2], v4[3]);
                }
            }
        }
        __syncthreads();
    }

    float inv[2] = {1.0f / l_i[0], 1.0f / l_i[1]};
    #pragma unroll
    for (int nt = 0; nt < 8; nt++) {
        #pragma unroll
        for (int jr = 0; jr < 2; jr++) {
            float v0 = oacc[nt][jr * 2 + 0] * inv[jr];
            float v1 = oacc[nt][jr * 2 + 1] * inv[jr];
            __half2 hv = __floats2half2_rn(v0, v1);
            size_t off = (rowbase + rowg0 + jr * 8) * DD + colq + nt * 8 + c2;
            *reinterpret_cast<uint32_t*>(O + off) = *reinterpret_cast<const uint32_t*>(&hv);
        }
    }
}

// ---------------- launch ----------------
extern "C" void kernel_launch(void* const* d_in, const int* in_sizes, int n_in,
                              void* d_out, int out_size) {
    const float* x     = (const float*)d_in[0];
    const float* ln1_g = (const float*)d_in[1];
    const float* ln1_b = (const float*)d_in[2];
    const float* Wq    = (const float*)d_in[3];
    const float* Wk    = (const float*)d_in[4];
    const float* Wv    = (const float*)d_in[5];
    const float* Wo    = (const float*)d_in[6];
    const float* bo    = (const float*)d_in[7];
    const float* ln2_g = (const float*)d_in[8];
    const float* ln2_b = (const float*)d_in[9];
    const float* W1    = (const float*)d_in[10];
    const float* b1    = (const float*)d_in[11];
    const float* W2    = (const float*)d_in[12];
    const float* b2    = (const float*)d_in[13];
    float* out = (float*)d_out;

    float* x2;
    cudaGetSymbolAddress((void**)&x2, g_x2);
    __half *h2, *q, *k, *v, *ctx, *mid;
    cudaGetSymbolAddress((void**)&h2, g_h2);
    cudaGetSymbolAddress((void**)&q, g_q);
    cudaGetSymbolAddress((void**)&k, g_k);
    cudaGetSymbolAddress((void**)&v, g_v);
    cudaGetSymbolAddress((void**)&ctx, g_ctx);
    cudaGetSymbolAddress((void**)&mid, g_mid);

    __half *wq, *wk, *wv, *wo, *w1, *w2;
    cudaGetSymbolAddress((void**)&wq, g_wq);
    cudaGetSymbolAddress((void**)&wk, g_wk);
    cudaGetSymbolAddress((void**)&wv, g_wv);
    cudaGetSymbolAddress((void**)&wo, g_wo);
    cudaGetSymbolAddress((void**)&w1, g_w1);
    cudaGetSymbolAddress((void**)&w2, g_w2);

    static int attr_set = 0;
    if (!attr_set) {
        cudaFuncSetAttribute(attn_mma_kernel, cudaFuncAttributeMaxDynamicSharedMemorySize, AT_SMEM);
        cudaFuncSetAttribute(gemm_qkv,  cudaFuncAttributeMaxDynamicSharedMemorySize, GEMM_SMEM);
        cudaFuncSetAttribute(gemm_f32,  cudaFuncAttributeMaxDynamicSharedMemorySize, GEMM_SMEM);
        cudaFuncSetAttribute(gemm_gelu, cudaFuncAttributeMaxDynamicSharedMemorySize, GEMM_SMEM);
        attr_set = 1;
    }

    const int M = MROWS;

    wsplit_all<<<12288, dim3(32, 8)>>>(Wq, Wk, Wv, Wo, W1, W2, wq, wk, wv, wo, w1, w2);

    ln_f16<<<M, 256>>>(x, ln1_g, ln1_b, h2);

    dim3 gQKV(DD / 128, M / 128, 3);
    gemm_qkv<<<gQKV, 128, GEMM_SMEM>>>(h2, wq, wk, wv, q, k, v);

    dim3 gA(SS / 128, BB * HH);
    attn_mma_kernel<<<gA, 256, AT_SMEM>>>(q, k, v, ctx);

    dim3 gDD(DD / 128, M / 128);
    gemm_f32<<<gDD, 128, GEMM_SMEM>>>(ctx, wo, x2, DD, DD, bo, x);

    ln_f16<<<M, 256>>>(x2, ln2_g, ln2_b, h2);

    dim3 gFF(DFF / 128, M / 128);
    gemm_gelu<<<gFF, 128, GEMM_SMEM>>>(h2, w1, mid, DFF, DD, b1);

    gemm_f32<<<gDD, 128, GEMM_SMEM>>>(mid, w2, out, DD, DFF, b2, x2);
}